// round 14
// baseline (speedup 1.0000x reference)
#include <cuda_runtime.h>
#include <cuda_bf16.h>
#include <cstdint>

#define HDIM 256
#define NMAX 50048

// ---------------- static scratch ----------------
__device__ float g_buf1[NMAX * HDIM];    // gemm2 out (msg) / gemm4 out (pre-LN)
__device__ float g_accum[NMAX * HDIM];   // scatter-sum
__device__ float g_counts[NMAX];
__device__ int   g_idx64;

// pre-split bf16 activations (hi/lo)
__device__ __nv_bfloat16 g_a0h[NMAX * 256], g_a0l[NMAX * 256];   // split(source)
__device__ __nv_bfloat16 g_a1h[NMAX * 256], g_a1l[NMAX * 256];   // gemm1 out
__device__ __nv_bfloat16 g_a3h[NMAX * 512], g_a3l[NMAX * 512];   // [target | accum/cnt]
__device__ __nv_bfloat16 g_a4h[NMAX * 256], g_a4l[NMAX * 256];   // gemm3 out

// split weights, transposed to [N, K] (K contiguous)
__device__ __nv_bfloat16 g_w0h[256 * 256], g_w0l[256 * 256];
__device__ __nv_bfloat16 g_w1h[256 * 256], g_w1l[256 * 256];
__device__ __nv_bfloat16 g_w2h[256 * 512], g_w2l[256 * 512];
__device__ __nv_bfloat16 g_w3h[256 * 256], g_w3l[256 * 256];

__device__ __forceinline__ float gelu_exact(float x) { return x * normcdff(x); }

__device__ __forceinline__ uint32_t smem_u32(const void* p) {
    uint32_t a;
    asm("{ .reg .u64 t; cvta.to.shared.u64 t, %1; cvt.u32.u64 %0, t; }" : "=r"(a) : "l"(p));
    return a;
}

#define LDMX4(r0, r1, r2, r3, a) \
    asm volatile("ldmatrix.sync.aligned.m8n8.x4.shared.b16 {%0,%1,%2,%3}, [%4];" \
        : "=r"(r0), "=r"(r1), "=r"(r2), "=r"(r3) : "r"(a))

#define MMA16816(c, a0, a1, a2, a3, b0, b1) \
    asm volatile("mma.sync.aligned.m16n8k16.row.col.f32.bf16.bf16.f32 " \
        "{%0,%1,%2,%3}, {%4,%5,%6,%7}, {%8,%9}, {%0,%1,%2,%3};" \
        : "+f"((c)[0]), "+f"((c)[1]), "+f"((c)[2]), "+f"((c)[3]) \
        : "r"(a0), "r"(a1), "r"(a2), "r"(a3), "r"(b0), "r"(b1))

#define CPASYNC16(sm, gp) \
    asm volatile("cp.async.cg.shared.global [%0], [%1], 16;" :: "r"(sm), "l"(gp))
#define CPASYNC_COMMIT() asm volatile("cp.async.commit_group;" ::: "memory")
#define CPASYNC_WAIT1()  asm volatile("cp.async.wait_group 1;" ::: "memory")

__device__ __forceinline__ uint32_t pack_bf2(__nv_bfloat16 a, __nv_bfloat16 b) {
    __nv_bfloat162 t = __halves2bfloat162(a, b);
    return *(uint32_t*)&t;
}
__device__ __forceinline__ void split2(float v0, float v1, uint32_t& hp, uint32_t& lp) {
    __nv_bfloat16 h0 = __float2bfloat16_rn(v0);
    __nv_bfloat16 h1 = __float2bfloat16_rn(v1);
    __nv_bfloat16 l0 = __float2bfloat16_rn(v0 - __bfloat162float(h0));
    __nv_bfloat16 l1 = __float2bfloat16_rn(v1 - __bfloat162float(h1));
    hp = pack_bf2(h0, h1);
    lp = pack_bf2(l0, l1);
}

// ---------------- small kernels ----------------
__global__ void detect_idx_kernel(const void* eidx, int nnodes) {
    const long long* p = (const long long*)eidx;
    int ok64 = 1;
    #pragma unroll 1
    for (int i = 0; i < 64; i++) {
        long long v = p[i];
        if (v < 0 || v >= (long long)nnodes) { ok64 = 0; break; }
    }
    g_idx64 = ok64;
}

__global__ void wprep_all_kernel(const float* __restrict__ W0,
                                 const float* __restrict__ W1,
                                 const float* __restrict__ W2,
                                 const float* __restrict__ W3) {
    int idx = blockIdx.x * blockDim.x + threadIdx.x;
    const float* W; __nv_bfloat16 *Wh, *Wl; int K;
    if (idx < 65536)       { W = W0; Wh = g_w0h; Wl = g_w0l; K = 256; }
    else if (idx < 131072) { W = W1; Wh = g_w1h; Wl = g_w1l; K = 256; idx -= 65536; }
    else if (idx < 262144) { W = W2; Wh = g_w2h; Wl = g_w2l; K = 512; idx -= 131072; }
    else if (idx < 327680) { W = W3; Wh = g_w3h; Wl = g_w3l; K = 256; idx -= 262144; }
    else return;
    const int n = idx / K, k = idx - n * K;
    const float w = W[(size_t)k * 256 + n];
    const __nv_bfloat16 h = __float2bfloat16_rn(w);
    Wh[idx] = h;
    Wl[idx] = __float2bfloat16_rn(w - __bfloat162float(h));
}

__global__ void split_src_kernel(const float* __restrict__ src,
                                 __nv_bfloat16* __restrict__ H,
                                 __nv_bfloat16* __restrict__ L, int n8) {
    const int i = blockIdx.x * blockDim.x + threadIdx.x;
    if (i >= n8) return;
    const float4 v0 = ((const float4*)src)[i * 2];
    const float4 v1 = ((const float4*)src)[i * 2 + 1];
    uint32_t h[4], l[4];
    split2(v0.x, v0.y, h[0], l[0]);
    split2(v0.z, v0.w, h[1], l[1]);
    split2(v1.x, v1.y, h[2], l[2]);
    split2(v1.z, v1.w, h[3], l[3]);
    ((uint4*)H)[i] = *(uint4*)h;
    ((uint4*)L)[i] = *(uint4*)l;
}

// build [M,512] hi/lo: cols 0-255 = target, 256-511 = accum/max(count,1)
__global__ void split_comb_kernel(const float* __restrict__ target,
                                  const float* __restrict__ accum,
                                  const float* __restrict__ counts, int M) {
    const int i = blockIdx.x * blockDim.x + threadIdx.x;
    if (i >= M * 64) return;
    const int row = i >> 6;
    const int c0 = (i & 63) * 8;
    float f[8];
    if (c0 < 256) {
        const float4 v0 = *(const float4*)(target + (size_t)row * 256 + c0);
        const float4 v1 = *(const float4*)(target + (size_t)row * 256 + c0 + 4);
        f[0] = v0.x; f[1] = v0.y; f[2] = v0.z; f[3] = v0.w;
        f[4] = v1.x; f[5] = v1.y; f[6] = v1.z; f[7] = v1.w;
    } else {
        const float inv = 1.0f / fmaxf(counts[row], 1.0f);
        const float4 v0 = *(const float4*)(accum + (size_t)row * 256 + (c0 - 256));
        const float4 v1 = *(const float4*)(accum + (size_t)row * 256 + (c0 - 256) + 4);
        f[0] = v0.x * inv; f[1] = v0.y * inv; f[2] = v0.z * inv; f[3] = v0.w * inv;
        f[4] = v1.x * inv; f[5] = v1.y * inv; f[6] = v1.z * inv; f[7] = v1.w * inv;
    }
    uint32_t h[4], l[4];
    #pragma unroll
    for (int j = 0; j < 4; j++) split2(f[2 * j], f[2 * j + 1], h[j], l[j]);
    ((uint4*)g_a3h)[i] = *(uint4*)h;
    ((uint4*)g_a3l)[i] = *(uint4*)l;
}

// ---------------- mma.sync GEMM with full fragment preload ----------------
// C = act(A @ Wt^T + b) [+resid]. A, Wt pre-split bf16 hi/lo.
// CTA 64x128, BK=32, 8 warps (2m x 4n), warp tile 32x32, 2 CTAs/SM.
// 3-stage fused A+B cp.async ring, one __syncthreads per chunk.
// All 16 LDMX4 for BOTH k16-halves issued before any MMA (LDSM latency
// hidden behind the load batch; asm-volatile order is program order).
#define STG_STRIDE 30720
#define SM_TOTAL (3 * STG_STRIDE)

template<int KCHUNKS, int OUTF32, int OUTSPLIT, int RESID>
__global__ __launch_bounds__(256, 2)
void gemm_bf16(const __nv_bfloat16* __restrict__ Ah, const __nv_bfloat16* __restrict__ Al,
               const __nv_bfloat16* __restrict__ Wh, const __nv_bfloat16* __restrict__ Wl,
               int Kw, const float* __restrict__ bias, const float* __restrict__ resid,
               float* __restrict__ Cf,
               __nv_bfloat16* __restrict__ Ch, __nv_bfloat16* __restrict__ Cl, int M)
{
    extern __shared__ char smem[];
    const uint32_t sb = smem_u32(smem);
    const int tid = threadIdx.x;
    const int wid = tid >> 5, lane = tid & 31;
    const int rowBlock = blockIdx.y * 64;
    const int colBlock = blockIdx.x * 128;

    const int warp_m = wid & 1;
    const int warp_n = wid >> 1;

    float acc[2][4][4];
    #pragma unroll
    for (int a = 0; a < 2; a++)
        #pragma unroll
        for (int b = 0; b < 4; b++)
            #pragma unroll
            for (int c = 0; c < 4; c++) acc[a][b][c] = 0.0f;

    const int a_rowin = (lane & 7) | (((lane >> 3) & 1) << 3);
    const int a_koff  = ((lane >> 4) & 1) * 8;
    const uint32_t a_byte = (uint32_t)((warp_m * 32 + a_rowin) * 80 + a_koff * 2);
    const int b_rowin = ((lane >> 4) & 1) * 8 + (lane & 7);
    const int b_koff  = ((lane >> 3) & 1) * 8;
    const uint32_t b_byte = (uint32_t)((warp_n * 32 + b_rowin) * 80 + b_koff * 2);

    const int a_row = tid >> 2, a_p = tid & 3;
    auto issueAB = [&](int ch) {
        if (ch < KCHUNKS) {
            const uint32_t base = sb + (uint32_t)(ch % 3) * STG_STRIDE;
            {
                const size_t g = (size_t)(rowBlock + a_row) * Kw + ch * 32 + a_p * 8;
                const uint32_t so = (uint32_t)(a_row * 80 + a_p * 16);
                CPASYNC16(base + so, Ah + g);
                CPASYNC16(base + 5120 + so, Al + g);
            }
            #pragma unroll
            for (int q = 0; q < 2; q++) {
                const int s2 = tid * 2 + q;
                const int n = s2 >> 2, p = s2 & 3;
                const size_t g = (size_t)(colBlock + n) * Kw + ch * 32 + p * 8;
                const uint32_t so = (uint32_t)(n * 80 + p * 16);
                CPASYNC16(base + 10240 + so, Wh + g);
                CPASYNC16(base + 20480 + so, Wl + g);
            }
        }
        CPASYNC_COMMIT();
    };

    issueAB(0);

    #pragma unroll 1
    for (int ch = 0; ch < KCHUNKS; ch++) {
        issueAB(ch + 1);
        CPASYNC_WAIT1();
        __syncthreads();

        const uint32_t stg = sb + (uint32_t)(ch % 3) * STG_STRIDE;
        const uint32_t aBase = stg + a_byte;
        const uint32_t bBase = stg + 10240 + b_byte;

        // ---- preload ALL fragments for both k16-halves ----
        uint32_t aH[2][2][4], aL[2][2][4], bh[2][2][4], bl[2][2][4]; // [s][frag][r]
        #pragma unroll
        for (int s = 0; s < 2; s++) {
            #pragma unroll
            for (int mt = 0; mt < 2; mt++) {
                LDMX4(aH[s][mt][0], aH[s][mt][1], aH[s][mt][2], aH[s][mt][3],
                      aBase + mt * 16 * 80 + s * 32);
                LDMX4(aL[s][mt][0], aL[s][mt][1], aL[s][mt][2], aL[s][mt][3],
                      aBase + 5120 + mt * 16 * 80 + s * 32);
            }
            #pragma unroll
            for (int np = 0; np < 2; np++) {
                LDMX4(bh[s][np][0], bh[s][np][1], bh[s][np][2], bh[s][np][3],
                      bBase + np * 16 * 80 + s * 32);
                LDMX4(bl[s][np][0], bl[s][np][1], bl[s][np][2], bl[s][np][3],
                      bBase + 10240 + np * 16 * 80 + s * 32);
            }
        }
        // ---- MMAs: 3 passes per s, 8 independent accumulators per pass ----
        #pragma unroll
        for (int s = 0; s < 2; s++) {
            #pragma unroll
            for (int mt = 0; mt < 2; mt++)
                #pragma unroll
                for (int nt = 0; nt < 4; nt++) {
                    const int np = nt >> 1, ix = (nt & 1) * 2;
                    MMA16816(acc[mt][nt], aH[s][mt][0], aH[s][mt][1], aH[s][mt][2], aH[s][mt][3],
                             bh[s][np][ix], bh[s][np][ix + 1]);
                }
            #pragma unroll
            for (int mt = 0; mt < 2; mt++)
                #pragma unroll
                for (int nt = 0; nt < 4; nt++) {
                    const int np = nt >> 1, ix = (nt & 1) * 2;
                    MMA16816(acc[mt][nt], aH[s][mt][0], aH[s][mt][1], aH[s][mt][2], aH[s][mt][3],
                             bl[s][np][ix], bl[s][np][ix + 1]);
                }
            #pragma unroll
            for (int mt = 0; mt < 2; mt++)
                #pragma unroll
                for (int nt = 0; nt < 4; nt++) {
                    const int np = nt >> 1, ix = (nt & 1) * 2;
                    MMA16816(acc[mt][nt], aL[s][mt][0], aL[s][mt][1], aL[s][mt][2], aL[s][mt][3],
                             bh[s][np][ix], bh[s][np][ix + 1]);
                }
        }
    }

    // ---- epilogue ----
    const int qr = lane >> 2;
    const int qc = (lane & 3) * 2;
    float bv[4][2];
    #pragma unroll
    for (int nt = 0; nt < 4; nt++) {
        const int col = colBlock + warp_n * 32 + nt * 8 + qc;
        bv[nt][0] = bias[col];
        bv[nt][1] = bias[col + 1];
    }
    #pragma unroll
    for (int mt = 0; mt < 2; mt++)
        #pragma unroll
        for (int half = 0; half < 2; half++) {
            const int row = rowBlock + warp_m * 32 + mt * 16 + qr + half * 8;
            if (row >= M) continue;
            #pragma unroll
            for (int nt = 0; nt < 4; nt++) {
                const int col = colBlock + warp_n * 32 + nt * 8 + qc;
                float v0 = gelu_exact(acc[mt][nt][half * 2 + 0] + bv[nt][0]);
                float v1 = gelu_exact(acc[mt][nt][half * 2 + 1] + bv[nt][1]);
                if (RESID) {
                    const float2 rv = *(const float2*)(resid + (size_t)row * 256 + col);
                    v0 += rv.x; v1 += rv.y;
                }
                if (OUTF32)
                    *(float2*)(Cf + (size_t)row * 256 + col) = make_float2(v0, v1);
                if (OUTSPLIT) {
                    uint32_t hp, lp;
                    split2(v0, v1, hp, lp);
                    *(uint32_t*)(Ch + (size_t)row * 256 + col) = hp;
                    *(uint32_t*)(Cl + (size_t)row * 256 + col) = lp;
                }
            }
        }
}

// ---------------- edge scatter-sum (2 edges per warp iteration) ----------------
__global__ void scatter_kernel(const void* __restrict__ eidx,
                               const float* __restrict__ msg,
                               float* __restrict__ accum,
                               float* __restrict__ counts,
                               int E, int Nn)
{
    const int lane = threadIdx.x & 31;
    const int warp = (blockIdx.x * blockDim.x + threadIdx.x) >> 5;
    const int nwarps = (gridDim.x * blockDim.x) >> 5;
    const int flag = g_idx64;
    const long long* p64 = (const long long*)eidx;
    const int*       p32 = (const int*)eidx;

    #pragma unroll 1
    for (int e = warp * 2; e < E; e += nwarps * 2) {
        const int e1ok = (e + 1 < E);
        int src0, dst0, src1 = 0, dst1 = 0;
        if (flag) {
            src0 = (int)p64[e]; dst0 = (int)p64[E + e];
            if (e1ok) { src1 = (int)p64[e + 1]; dst1 = (int)p64[E + e + 1]; }
        } else {
            src0 = p32[e]; dst0 = p32[E + e];
            if (e1ok) { src1 = p32[e + 1]; dst1 = p32[E + e + 1]; }
        }
        src0 = min(max(src0, 0), Nn - 1); dst0 = min(max(dst0, 0), Nn - 1);
        src1 = min(max(src1, 0), Nn - 1); dst1 = min(max(dst1, 0), Nn - 1);

        const float4* s0 = (const float4*)(msg + (size_t)src0 * 256);
        const float4* s1 = (const float4*)(msg + (size_t)src1 * 256);
        const float4 a0 = s0[lane * 2 + 0];
        const float4 a1 = s0[lane * 2 + 1];
        float4 b0 = make_float4(0.f, 0.f, 0.f, 0.f);
        float4 b1 = make_float4(0.f, 0.f, 0.f, 0.f);
        if (e1ok) { b0 = s1[lane * 2 + 0]; b1 = s1[lane * 2 + 1]; }

        float* d0 = accum + (size_t)dst0 * 256 + lane * 8;
        asm volatile("red.global.add.v4.f32 [%0], {%1,%2,%3,%4};"
                     :: "l"(d0), "f"(a0.x), "f"(a0.y), "f"(a0.z), "f"(a0.w) : "memory");
        asm volatile("red.global.add.v4.f32 [%0], {%1,%2,%3,%4};"
                     :: "l"(d0 + 4), "f"(a1.x), "f"(a1.y), "f"(a1.z), "f"(a1.w) : "memory");
        if (e1ok) {
            float* d1 = accum + (size_t)dst1 * 256 + lane * 8;
            asm volatile("red.global.add.v4.f32 [%0], {%1,%2,%3,%4};"
                         :: "l"(d1), "f"(b0.x), "f"(b0.y), "f"(b0.z), "f"(b0.w) : "memory");
            asm volatile("red.global.add.v4.f32 [%0], {%1,%2,%3,%4};"
                         :: "l"(d1 + 4), "f"(b1.x), "f"(b1.y), "f"(b1.z), "f"(b1.w) : "memory");
        }
        if (lane == 0) {
            asm volatile("red.global.add.f32 [%0], %1;"
                         :: "l"(counts + dst0), "f"(1.0f) : "memory");
            if (e1ok)
                asm volatile("red.global.add.f32 [%0], %1;"
                             :: "l"(counts + dst1), "f"(1.0f) : "memory");
        }
    }
}

// ---------------- LayerNorm (warp per row) ----------------
__global__ __launch_bounds__(256)
void ln_kernel(const float* __restrict__ X, const float* __restrict__ gamma,
               const float* __restrict__ beta, float* __restrict__ out, int M)
{
    const int warp = (blockIdx.x * blockDim.x + threadIdx.x) >> 5;
    const int lane = threadIdx.x & 31;
    if (warp >= M) return;
    const float* xp = X + (size_t)warp * 256 + lane * 8;
    float v[8];
    *(float4*)&v[0] = *(const float4*)(xp);
    *(float4*)&v[4] = *(const float4*)(xp + 4);
    float s = 0.f, sq = 0.f;
    #pragma unroll
    for (int j = 0; j < 8; j++) { s += v[j]; sq += v[j] * v[j]; }
    #pragma unroll
    for (int off = 16; off > 0; off >>= 1) {
        s  += __shfl_xor_sync(0xFFFFFFFFu, s,  off);
        sq += __shfl_xor_sync(0xFFFFFFFFu, sq, off);
    }
    const float mu  = s * (1.0f / 256.0f);
    const float var = sq * (1.0f / 256.0f) - mu * mu;
    const float inv = rsqrtf(var + 1e-5f);
    float o[8];
    #pragma unroll
    for (int j = 0; j < 8; j++)
        o[j] = (v[j] - mu) * inv * gamma[lane * 8 + j] + beta[lane * 8 + j];
    float* dp = out + (size_t)warp * 256 + lane * 8;
    *(float4*)(dp)     = *(float4*)&o[0];
    *(float4*)(dp + 4) = *(float4*)&o[4];
}

// ---------------- launch ----------------
extern "C" void kernel_launch(void* const* d_in, const int* in_sizes, int n_in,
                              void* d_out, int out_size)
{
    const float* source = (const float*)d_in[0];
    const float* target = (const float*)d_in[1];
    const void*  eidx   = d_in[2];
    const int base = (n_in > 3 && in_sizes[3] == 1) ? 4 : 3;
    const float* W0 = (const float*)d_in[base + 0];
    const float* b0 = (const float*)d_in[base + 1];
    const float* W1 = (const float*)d_in[base + 2];
    const float* b1 = (const float*)d_in[base + 3];
    const float* W2 = (const float*)d_in[base + 4];
    const float* b2 = (const float*)d_in[base + 5];
    const float* W3 = (const float*)d_in[base + 6];
    const float* b3 = (const float*)d_in[base + 7];
    const float* gm = (const float*)d_in[base + 8];
    const float* bt = (const float*)d_in[base + 9];

    const int M = in_sizes[0] / HDIM;
    const int E = in_sizes[2] / 2;

    float *buf1, *accum, *counts;
    cudaGetSymbolAddress((void**)&buf1,   g_buf1);
    cudaGetSymbolAddress((void**)&accum,  g_accum);
    cudaGetSymbolAddress((void**)&counts, g_counts);
    __nv_bfloat16 *a0h, *a0l, *a1h, *a1l, *a3h, *a3l, *a4h, *a4l;
    cudaGetSymbolAddress((void**)&a0h, g_a0h); cudaGetSymbolAddress((void**)&a0l, g_a0l);
    cudaGetSymbolAddress((void**)&a1h, g_a1h); cudaGetSymbolAddress((void**)&a1l, g_a1l);
    cudaGetSymbolAddress((void**)&a3h, g_a3h); cudaGetSymbolAddress((void**)&a3l, g_a3l);
    cudaGetSymbolAddress((void**)&a4h, g_a4h); cudaGetSymbolAddress((void**)&a4l, g_a4l);
    __nv_bfloat16 *w0h, *w0l, *w1h, *w1l, *w2h, *w2l, *w3h, *w3l;
    cudaGetSymbolAddress((void**)&w0h, g_w0h); cudaGetSymbolAddress((void**)&w0l, g_w0l);
    cudaGetSymbolAddress((void**)&w1h, g_w1h); cudaGetSymbolAddress((void**)&w1l, g_w1l);
    cudaGetSymbolAddress((void**)&w2h, g_w2h); cudaGetSymbolAddress((void**)&w2l, g_w2l);
    cudaGetSymbolAddress((void**)&w3h, g_w3h); cudaGetSymbolAddress((void**)&w3l, g_w3l);

    cudaFuncSetAttribute(gemm_bf16<8, 0, 1, 0>,  cudaFuncAttributeMaxDynamicSharedMemorySize, SM_TOTAL);
    cudaFuncSetAttribute(gemm_bf16<8, 1, 0, 0>,  cudaFuncAttributeMaxDynamicSharedMemorySize, SM_TOTAL);
    cudaFuncSetAttribute(gemm_bf16<16, 0, 1, 0>, cudaFuncAttributeMaxDynamicSharedMemorySize, SM_TOTAL);
    cudaFuncSetAttribute(gemm_bf16<8, 1, 0, 1>,  cudaFuncAttributeMaxDynamicSharedMemorySize, SM_TOTAL);

    // Launch order keeps ncu "-s 5 -c 1" on gemm1:
    //  0 memset, 1 memset, 2 wprep, 3 detect, 4 split_src, 5 gemm1 <- captured
    cudaMemsetAsync(accum, 0, sizeof(float) * (size_t)M * HDIM);
    cudaMemsetAsync(counts, 0, sizeof(float) * (size_t)M);
    wprep_all_kernel<<<(327680 + 255) / 256, 256>>>(W0, W1, W2, W3);
    detect_idx_kernel<<<1, 1>>>(eidx, M);
    split_src_kernel<<<(M * 32 + 255) / 256, 256>>>(source, a0h, a0l, M * 32);

    const dim3 gG(2, (M + 63) / 64);
    gemm_bf16<8, 0, 1, 0><<<gG, 256, SM_TOTAL>>>(a0h, a0l, w0h, w0l, 256, b0, nullptr,
                                                 nullptr, a1h, a1l, M);
    gemm_bf16<8, 1, 0, 0><<<gG, 256, SM_TOTAL>>>(a1h, a1l, w1h, w1l, 256, b1, nullptr,
                                                 buf1, nullptr, nullptr, M);

    scatter_kernel<<<2960, 256>>>(eidx, buf1, accum, counts, E, M);

    split_comb_kernel<<<(M * 64 + 255) / 256, 256>>>(target, accum, counts, M);

    gemm_bf16<16, 0, 1, 0><<<gG, 256, SM_TOTAL>>>(a3h, a3l, w2h, w2l, 512, b2, nullptr,
                                                  nullptr, a4h, a4l, M);
    gemm_bf16<8, 1, 0, 1><<<gG, 256, SM_TOTAL>>>(a4h, a4l, w3h, w3l, 256, b3, target,
                                                 buf1, nullptr, nullptr, M);

    ln_kernel<<<(M * 32 + 255) / 256, 256>>>(buf1, gm, bt, (float*)d_out, M);
}

// round 15
// speedup vs baseline: 1.0092x; 1.0092x over previous
#include <cuda_runtime.h>
#include <cuda_bf16.h>
#include <cstdint>

#define HDIM 256
#define NMAX 50048

// ---------------- static scratch ----------------
__device__ float g_buf1[NMAX * HDIM];    // gemm2 out (msg) / gemm4 out (pre-LN)
__device__ float g_accum[NMAX * HDIM];   // scatter-sum
__device__ float g_counts[NMAX];
__device__ int   g_idx64;

// pre-split bf16 activations (hi/lo) produced by GEMM epilogues
__device__ __nv_bfloat16 g_a1h[NMAX * 256], g_a1l[NMAX * 256];   // gemm1 out
__device__ __nv_bfloat16 g_a4h[NMAX * 256], g_a4l[NMAX * 256];   // gemm3 out

// split weights, transposed to [N, K] (K contiguous)
__device__ __nv_bfloat16 g_w0h[256 * 256], g_w0l[256 * 256];
__device__ __nv_bfloat16 g_w1h[256 * 256], g_w1l[256 * 256];
__device__ __nv_bfloat16 g_w2h[256 * 512], g_w2l[256 * 512];
__device__ __nv_bfloat16 g_w3h[256 * 256], g_w3l[256 * 256];

__device__ __forceinline__ float gelu_exact(float x) { return x * normcdff(x); }

__device__ __forceinline__ uint32_t smem_u32(const void* p) {
    uint32_t a;
    asm("{ .reg .u64 t; cvta.to.shared.u64 t, %1; cvt.u32.u64 %0, t; }" : "=r"(a) : "l"(p));
    return a;
}

#define LDMX4(r0, r1, r2, r3, a) \
    asm volatile("ldmatrix.sync.aligned.m8n8.x4.shared.b16 {%0,%1,%2,%3}, [%4];" \
        : "=r"(r0), "=r"(r1), "=r"(r2), "=r"(r3) : "r"(a))

#define MMA16816(c, a0, a1, a2, a3, b0, b1) \
    asm volatile("mma.sync.aligned.m16n8k16.row.col.f32.bf16.bf16.f32 " \
        "{%0,%1,%2,%3}, {%4,%5,%6,%7}, {%8,%9}, {%0,%1,%2,%3};" \
        : "+f"((c)[0]), "+f"((c)[1]), "+f"((c)[2]), "+f"((c)[3]) \
        : "r"(a0), "r"(a1), "r"(a2), "r"(a3), "r"(b0), "r"(b1))

#define CPASYNC16(sm, gp) \
    asm volatile("cp.async.cg.shared.global [%0], [%1], 16;" :: "r"(sm), "l"(gp))
#define CPASYNC_COMMIT() asm volatile("cp.async.commit_group;" ::: "memory")
#define CPASYNC_WAIT1()  asm volatile("cp.async.wait_group 1;" ::: "memory")
#define CPASYNC_WAIT2()  asm volatile("cp.async.wait_group 2;" ::: "memory")

__device__ __forceinline__ uint32_t pack_bf2(__nv_bfloat16 a, __nv_bfloat16 b) {
    __nv_bfloat162 t = __halves2bfloat162(a, b);
    return *(uint32_t*)&t;
}
__device__ __forceinline__ void split2(float v0, float v1, uint32_t& hp, uint32_t& lp) {
    __nv_bfloat16 h0 = __float2bfloat16_rn(v0);
    __nv_bfloat16 h1 = __float2bfloat16_rn(v1);
    __nv_bfloat16 l0 = __float2bfloat16_rn(v0 - __bfloat162float(h0));
    __nv_bfloat16 l1 = __float2bfloat16_rn(v1 - __bfloat162float(h1));
    hp = pack_bf2(h0, h1);
    lp = pack_bf2(l0, l1);
}

// ---------------- small kernels ----------------
__global__ void detect_idx_kernel(const void* eidx, int nnodes) {
    const long long* p = (const long long*)eidx;
    int ok64 = 1;
    #pragma unroll 1
    for (int i = 0; i < 64; i++) {
        long long v = p[i];
        if (v < 0 || v >= (long long)nnodes) { ok64 = 0; break; }
    }
    g_idx64 = ok64;
}

__global__ void wprep_all_kernel(const float* __restrict__ W0,
                                 const float* __restrict__ W1,
                                 const float* __restrict__ W2,
                                 const float* __restrict__ W3) {
    int idx = blockIdx.x * blockDim.x + threadIdx.x;
    const float* W; __nv_bfloat16 *Wh, *Wl; int K;
    if (idx < 65536)       { W = W0; Wh = g_w0h; Wl = g_w0l; K = 256; }
    else if (idx < 131072) { W = W1; Wh = g_w1h; Wl = g_w1l; K = 256; idx -= 65536; }
    else if (idx < 262144) { W = W2; Wh = g_w2h; Wl = g_w2l; K = 512; idx -= 131072; }
    else if (idx < 327680) { W = W3; Wh = g_w3h; Wl = g_w3l; K = 256; idx -= 262144; }
    else return;
    const int n = idx / K, k = idx - n * K;
    const float w = W[(size_t)k * 256 + n];
    const __nv_bfloat16 h = __float2bfloat16_rn(w);
    Wh[idx] = h;
    Wl[idx] = __float2bfloat16_rn(w - __bfloat162float(h));
}

// ============ GEMM variant 1: fp32 A input, in-loop split (R10-proven) ============
// CTA 64x128, BK=32, 8 warps (2m x 4n), warp tile 32x32, 2 CTAs/SM.
// A double-buffer (reg-staged convert), B 4-stage cp.async ring, one sync.
// SPLIT: k<256 from A, k>=256 from A2 * 1/max(count,1).
// OUTSPLIT: epilogue writes bf16 hi/lo; else fp32.
#define F_SA_BASE 0
#define F_SA_STAGE 10240
#define F_HLA_OFF 5120
#define F_SB_BASE 20480
#define F_SB_STAGE 20480
#define F_HLB_OFF 10240
#define F_SM_TOTAL 102400

template<int KCHUNKS, int SPLIT, int OUTSPLIT>
__global__ __launch_bounds__(256, 2)
void gemm_f32in(const float* __restrict__ A, const float* __restrict__ A2,
                const float* __restrict__ counts,
                const __nv_bfloat16* __restrict__ Wh, const __nv_bfloat16* __restrict__ Wl,
                int Kw, const float* __restrict__ bias,
                float* __restrict__ Cf,
                __nv_bfloat16* __restrict__ Ch, __nv_bfloat16* __restrict__ Cl, int M)
{
    extern __shared__ char smem[];
    const uint32_t sb = smem_u32(smem);
    const int tid = threadIdx.x;
    const int wid = tid >> 5, lane = tid & 31;
    const int rowBlock = blockIdx.y * 64;
    const int colBlock = blockIdx.x * 128;

    const int warp_m = wid & 1;
    const int warp_n = wid >> 1;

    float acc[2][4][4];
    #pragma unroll
    for (int a = 0; a < 2; a++)
        #pragma unroll
        for (int b = 0; b < 4; b++)
            #pragma unroll
            for (int c = 0; c < 4; c++) acc[a][b][c] = 0.0f;

    const int arow = tid >> 2;
    const int acb  = (tid & 3) * 8;

    const int a_rowin = (lane & 7) | (((lane >> 3) & 1) << 3);
    const int a_koff  = ((lane >> 4) & 1) * 8;
    const uint32_t a_byte = (uint32_t)((warp_m * 32 + a_rowin) * 80 + a_koff * 2);
    const int b_rowin = ((lane >> 4) & 1) * 8 + (lane & 7);
    const int b_koff  = ((lane >> 3) & 1) * 8;
    const uint32_t b_byte = (uint32_t)((warp_n * 32 + b_rowin) * 80 + b_koff * 2);

    float ar[8];
    auto loadA = [&](int ch) {
        const int gr = rowBlock + arow;
        #pragma unroll
        for (int j = 0; j < 8; j++) ar[j] = 0.0f;
        if (gr < M) {
            const int gk = ch * 32 + acb;
            const float* src;
            float sc = 1.0f;
            if (SPLIT && gk >= 256) {
                src = A2 + (size_t)gr * 256 + (gk - 256);
                sc = 1.0f / fmaxf(counts[gr], 1.0f);
            } else {
                src = A + (size_t)gr * 256 + gk;
            }
            float4 v0 = *(const float4*)src;
            float4 v1 = *(const float4*)(src + 4);
            ar[0] = v0.x * sc; ar[1] = v0.y * sc; ar[2] = v0.z * sc; ar[3] = v0.w * sc;
            ar[4] = v1.x * sc; ar[5] = v1.y * sc; ar[6] = v1.z * sc; ar[7] = v1.w * sc;
        }
    };
    auto storeA = [&](int stA) {
        uint32_t hp[4], lp[4];
        #pragma unroll
        for (int j = 0; j < 4; j++) split2(ar[2 * j], ar[2 * j + 1], hp[j], lp[j]);
        const uint32_t off = (uint32_t)(F_SA_BASE + stA * F_SA_STAGE + arow * 80 + acb * 2);
        *(uint4*)(smem + off)             = *(uint4*)&hp[0];
        *(uint4*)(smem + off + F_HLA_OFF) = *(uint4*)&lp[0];
    };
    auto issueB = [&](int ch) {
        if (ch < KCHUNKS) {
            const int st = ch & 3;
            const uint32_t bh = sb + F_SB_BASE + st * F_SB_STAGE;
            #pragma unroll
            for (int q = 0; q < 2; q++) {
                const int s = tid * 2 + q;
                const int n = s >> 2, p = s & 3;
                const size_t gofs = (size_t)(colBlock + n) * Kw + ch * 32 + p * 8;
                const uint32_t so = (uint32_t)(n * 80 + p * 16);
                CPASYNC16(bh + so, Wh + gofs);
                CPASYNC16(bh + F_HLB_OFF + so, Wl + gofs);
            }
        }
        CPASYNC_COMMIT();
    };

    issueB(0);
    issueB(1);
    loadA(0);
    storeA(0);

    #pragma unroll 1
    for (int ch = 0; ch < KCHUNKS; ch++) {
        issueB(ch + 2);
        const bool more = (ch + 1 < KCHUNKS);
        if (more) loadA(ch + 1);
        CPASYNC_WAIT2();
        __syncthreads();

        const uint32_t aBase = sb + F_SA_BASE + (ch & 1) * F_SA_STAGE + a_byte;
        const uint32_t bBase = sb + F_SB_BASE + (ch & 3) * F_SB_STAGE + b_byte;
        #pragma unroll
        for (int s = 0; s < 2; s++) {
            uint32_t ah[4], al[4], bh[2][4], bl[2][4];
            LDMX4(ah[0], ah[1], ah[2], ah[3], aBase + s * 32);
            LDMX4(al[0], al[1], al[2], al[3], aBase + F_HLA_OFF + s * 32);
            #pragma unroll
            for (int np = 0; np < 2; np++) {
                LDMX4(bh[np][0], bh[np][1], bh[np][2], bh[np][3], bBase + np * 16 * 80 + s * 32);
                LDMX4(bl[np][0], bl[np][1], bl[np][2], bl[np][3], bBase + F_HLB_OFF + np * 16 * 80 + s * 32);
            }
            uint32_t ah2[4], al2[4];
            LDMX4(ah2[0], ah2[1], ah2[2], ah2[3], aBase + 16 * 80 + s * 32);
            LDMX4(al2[0], al2[1], al2[2], al2[3], aBase + F_HLA_OFF + 16 * 80 + s * 32);
            #pragma unroll
            for (int nt = 0; nt < 4; nt++) {
                const int np = nt >> 1, ix = (nt & 1) * 2;
                MMA16816(acc[0][nt], ah[0], ah[1], ah[2], ah[3], bh[np][ix], bh[np][ix + 1]);
                MMA16816(acc[0][nt], ah[0], ah[1], ah[2], ah[3], bl[np][ix], bl[np][ix + 1]);
                MMA16816(acc[0][nt], al[0], al[1], al[2], al[3], bh[np][ix], bh[np][ix + 1]);
                MMA16816(acc[1][nt], ah2[0], ah2[1], ah2[2], ah2[3], bh[np][ix], bh[np][ix + 1]);
                MMA16816(acc[1][nt], ah2[0], ah2[1], ah2[2], ah2[3], bl[np][ix], bl[np][ix + 1]);
                MMA16816(acc[1][nt], al2[0], al2[1], al2[2], al2[3], bh[np][ix], bh[np][ix + 1]);
            }
        }
        if (more) storeA((ch + 1) & 1);
    }

    const int qr = lane >> 2;
    const int qc = (lane & 3) * 2;
    float bv[4][2];
    #pragma unroll
    for (int nt = 0; nt < 4; nt++) {
        const int col = colBlock + warp_n * 32 + nt * 8 + qc;
        bv[nt][0] = bias[col];
        bv[nt][1] = bias[col + 1];
    }
    #pragma unroll
    for (int mt = 0; mt < 2; mt++)
        #pragma unroll
        for (int half = 0; half < 2; half++) {
            const int row = rowBlock + warp_m * 32 + mt * 16 + qr + half * 8;
            if (row >= M) continue;
            #pragma unroll
            for (int nt = 0; nt < 4; nt++) {
                const int col = colBlock + warp_n * 32 + nt * 8 + qc;
                float v0 = gelu_exact(acc[mt][nt][half * 2 + 0] + bv[nt][0]);
                float v1 = gelu_exact(acc[mt][nt][half * 2 + 1] + bv[nt][1]);
                if (OUTSPLIT) {
                    uint32_t hp, lp;
                    split2(v0, v1, hp, lp);
                    *(uint32_t*)(Ch + (size_t)row * 256 + col) = hp;
                    *(uint32_t*)(Cl + (size_t)row * 256 + col) = lp;
                } else {
                    *(float2*)(Cf + (size_t)row * 256 + col) = make_float2(v0, v1);
                }
            }
        }
}

// ============ GEMM variant 2: pre-split bf16 A input (R14-proven) ============
#define B_STG_STRIDE 30720
#define B_SM_TOTAL (3 * B_STG_STRIDE)

template<int KCHUNKS, int OUTSPLIT, int RESID>
__global__ __launch_bounds__(256, 2)
void gemm_bf16in(const __nv_bfloat16* __restrict__ Ah, const __nv_bfloat16* __restrict__ Al,
                 const __nv_bfloat16* __restrict__ Wh, const __nv_bfloat16* __restrict__ Wl,
                 int Kw, const float* __restrict__ bias, const float* __restrict__ resid,
                 float* __restrict__ Cf,
                 __nv_bfloat16* __restrict__ Ch, __nv_bfloat16* __restrict__ Cl, int M)
{
    extern __shared__ char smem[];
    const uint32_t sb = smem_u32(smem);
    const int tid = threadIdx.x;
    const int wid = tid >> 5, lane = tid & 31;
    const int rowBlock = blockIdx.y * 64;
    const int colBlock = blockIdx.x * 128;

    const int warp_m = wid & 1;
    const int warp_n = wid >> 1;

    float acc[2][4][4];
    #pragma unroll
    for (int a = 0; a < 2; a++)
        #pragma unroll
        for (int b = 0; b < 4; b++)
            #pragma unroll
            for (int c = 0; c < 4; c++) acc[a][b][c] = 0.0f;

    const int a_rowin = (lane & 7) | (((lane >> 3) & 1) << 3);
    const int a_koff  = ((lane >> 4) & 1) * 8;
    const uint32_t a_byte = (uint32_t)((warp_m * 32 + a_rowin) * 80 + a_koff * 2);
    const int b_rowin = ((lane >> 4) & 1) * 8 + (lane & 7);
    const int b_koff  = ((lane >> 3) & 1) * 8;
    const uint32_t b_byte = (uint32_t)((warp_n * 32 + b_rowin) * 80 + b_koff * 2);

    const int a_row = tid >> 2, a_p = tid & 3;
    auto issueAB = [&](int ch) {
        if (ch < KCHUNKS) {
            const uint32_t base = sb + (uint32_t)(ch % 3) * B_STG_STRIDE;
            {
                const size_t g = (size_t)(rowBlock + a_row) * Kw + ch * 32 + a_p * 8;
                const uint32_t so = (uint32_t)(a_row * 80 + a_p * 16);
                CPASYNC16(base + so, Ah + g);
                CPASYNC16(base + 5120 + so, Al + g);
            }
            #pragma unroll
            for (int q = 0; q < 2; q++) {
                const int s2 = tid * 2 + q;
                const int n = s2 >> 2, p = s2 & 3;
                const size_t g = (size_t)(colBlock + n) * Kw + ch * 32 + p * 8;
                const uint32_t so = (uint32_t)(n * 80 + p * 16);
                CPASYNC16(base + 10240 + so, Wh + g);
                CPASYNC16(base + 20480 + so, Wl + g);
            }
        }
        CPASYNC_COMMIT();
    };

    issueAB(0);

    #pragma unroll 1
    for (int ch = 0; ch < KCHUNKS; ch++) {
        issueAB(ch + 1);
        CPASYNC_WAIT1();
        __syncthreads();

        const uint32_t stg = sb + (uint32_t)(ch % 3) * B_STG_STRIDE;
        const uint32_t aBase = stg + a_byte;
        const uint32_t bBase = stg + 10240 + b_byte;
        #pragma unroll
        for (int s = 0; s < 2; s++) {
            uint32_t ah[4], al[4], bh[2][4], bl[2][4];
            LDMX4(ah[0], ah[1], ah[2], ah[3], aBase + s * 32);
            LDMX4(al[0], al[1], al[2], al[3], aBase + 5120 + s * 32);
            #pragma unroll
            for (int np = 0; np < 2; np++) {
                LDMX4(bh[np][0], bh[np][1], bh[np][2], bh[np][3], bBase + np * 16 * 80 + s * 32);
                LDMX4(bl[np][0], bl[np][1], bl[np][2], bl[np][3], bBase + 10240 + np * 16 * 80 + s * 32);
            }
            uint32_t ah2[4], al2[4];
            LDMX4(ah2[0], ah2[1], ah2[2], ah2[3], aBase + 16 * 80 + s * 32);
            LDMX4(al2[0], al2[1], al2[2], al2[3], aBase + 5120 + 16 * 80 + s * 32);
            #pragma unroll
            for (int nt = 0; nt < 4; nt++) {
                const int np = nt >> 1, ix = (nt & 1) * 2;
                MMA16816(acc[0][nt], ah[0], ah[1], ah[2], ah[3], bh[np][ix], bh[np][ix + 1]);
                MMA16816(acc[0][nt], ah[0], ah[1], ah[2], ah[3], bl[np][ix], bl[np][ix + 1]);
                MMA16816(acc[0][nt], al[0], al[1], al[2], al[3], bh[np][ix], bh[np][ix + 1]);
                MMA16816(acc[1][nt], ah2[0], ah2[1], ah2[2], ah2[3], bh[np][ix], bh[np][ix + 1]);
                MMA16816(acc[1][nt], ah2[0], ah2[1], ah2[2], ah2[3], bl[np][ix], bl[np][ix + 1]);
                MMA16816(acc[1][nt], al2[0], al2[1], al2[2], al2[3], bh[np][ix], bh[np][ix + 1]);
            }
        }
    }

    const int qr = lane >> 2;
    const int qc = (lane & 3) * 2;
    float bv[4][2];
    #pragma unroll
    for (int nt = 0; nt < 4; nt++) {
        const int col = colBlock + warp_n * 32 + nt * 8 + qc;
        bv[nt][0] = bias[col];
        bv[nt][1] = bias[col + 1];
    }
    #pragma unroll
    for (int mt = 0; mt < 2; mt++)
        #pragma unroll
        for (int half = 0; half < 2; half++) {
            const int row = rowBlock + warp_m * 32 + mt * 16 + qr + half * 8;
            if (row >= M) continue;
            #pragma unroll
            for (int nt = 0; nt < 4; nt++) {
                const int col = colBlock + warp_n * 32 + nt * 8 + qc;
                float v0 = gelu_exact(acc[mt][nt][half * 2 + 0] + bv[nt][0]);
                float v1 = gelu_exact(acc[mt][nt][half * 2 + 1] + bv[nt][1]);
                if (RESID) {
                    const float2 rv = *(const float2*)(resid + (size_t)row * 256 + col);
                    v0 += rv.x; v1 += rv.y;
                }
                if (OUTSPLIT) {
                    uint32_t hp, lp;
                    split2(v0, v1, hp, lp);
                    *(uint32_t*)(Ch + (size_t)row * 256 + col) = hp;
                    *(uint32_t*)(Cl + (size_t)row * 256 + col) = lp;
                } else {
                    *(float2*)(Cf + (size_t)row * 256 + col) = make_float2(v0, v1);
                }
            }
        }
}

// ---------------- edge scatter-sum (2 edges per warp iteration) ----------------
__global__ void scatter_kernel(const void* __restrict__ eidx,
                               const float* __restrict__ msg,
                               float* __restrict__ accum,
                               float* __restrict__ counts,
                               int E, int Nn)
{
    const int lane = threadIdx.x & 31;
    const int warp = (blockIdx.x * blockDim.x + threadIdx.x) >> 5;
    const int nwarps = (gridDim.x * blockDim.x) >> 5;
    const int flag = g_idx64;
    const long long* p64 = (const long long*)eidx;
    const int*       p32 = (const int*)eidx;

    #pragma unroll 1
    for (int e = warp * 2; e < E; e += nwarps * 2) {
        const int e1ok = (e + 1 < E);
        int src0, dst0, src1 = 0, dst1 = 0;
        if (flag) {
            src0 = (int)p64[e]; dst0 = (int)p64[E + e];
            if (e1ok) { src1 = (int)p64[e + 1]; dst1 = (int)p64[E + e + 1]; }
        } else {
            src0 = p32[e]; dst0 = p32[E + e];
            if (e1ok) { src1 = p32[e + 1]; dst1 = p32[E + e + 1]; }
        }
        src0 = min(max(src0, 0), Nn - 1); dst0 = min(max(dst0, 0), Nn - 1);
        src1 = min(max(src1, 0), Nn - 1); dst1 = min(max(dst1, 0), Nn - 1);

        const float4* s0 = (const float4*)(msg + (size_t)src0 * 256);
        const float4* s1 = (const float4*)(msg + (size_t)src1 * 256);
        const float4 a0 = s0[lane * 2 + 0];
        const float4 a1 = s0[lane * 2 + 1];
        float4 b0 = make_float4(0.f, 0.f, 0.f, 0.f);
        float4 b1 = make_float4(0.f, 0.f, 0.f, 0.f);
        if (e1ok) { b0 = s1[lane * 2 + 0]; b1 = s1[lane * 2 + 1]; }

        float* d0 = accum + (size_t)dst0 * 256 + lane * 8;
        asm volatile("red.global.add.v4.f32 [%0], {%1,%2,%3,%4};"
                     :: "l"(d0), "f"(a0.x), "f"(a0.y), "f"(a0.z), "f"(a0.w) : "memory");
        asm volatile("red.global.add.v4.f32 [%0], {%1,%2,%3,%4};"
                     :: "l"(d0 + 4), "f"(a1.x), "f"(a1.y), "f"(a1.z), "f"(a1.w) : "memory");
        if (e1ok) {
            float* d1 = accum + (size_t)dst1 * 256 + lane * 8;
            asm volatile("red.global.add.v4.f32 [%0], {%1,%2,%3,%4};"
                         :: "l"(d1), "f"(b0.x), "f"(b0.y), "f"(b0.z), "f"(b0.w) : "memory");
            asm volatile("red.global.add.v4.f32 [%0], {%1,%2,%3,%4};"
                         :: "l"(d1 + 4), "f"(b1.x), "f"(b1.y), "f"(b1.z), "f"(b1.w) : "memory");
        }
        if (lane == 0) {
            asm volatile("red.global.add.f32 [%0], %1;"
                         :: "l"(counts + dst0), "f"(1.0f) : "memory");
            if (e1ok)
                asm volatile("red.global.add.f32 [%0], %1;"
                             :: "l"(counts + dst1), "f"(1.0f) : "memory");
        }
    }
}

// ---------------- LayerNorm (warp per row) ----------------
__global__ __launch_bounds__(256)
void ln_kernel(const float* __restrict__ X, const float* __restrict__ gamma,
               const float* __restrict__ beta, float* __restrict__ out, int M)
{
    const int warp = (blockIdx.x * blockDim.x + threadIdx.x) >> 5;
    const int lane = threadIdx.x & 31;
    if (warp >= M) return;
    const float* xp = X + (size_t)warp * 256 + lane * 8;
    float v[8];
    *(float4*)&v[0] = *(const float4*)(xp);
    *(float4*)&v[4] = *(const float4*)(xp + 4);
    float s = 0.f, sq = 0.f;
    #pragma unroll
    for (int j = 0; j < 8; j++) { s += v[j]; sq += v[j] * v[j]; }
    #pragma unroll
    for (int off = 16; off > 0; off >>= 1) {
        s  += __shfl_xor_sync(0xFFFFFFFFu, s,  off);
        sq += __shfl_xor_sync(0xFFFFFFFFu, sq, off);
    }
    const float mu  = s * (1.0f / 256.0f);
    const float var = sq * (1.0f / 256.0f) - mu * mu;
    const float inv = rsqrtf(var + 1e-5f);
    float o[8];
    #pragma unroll
    for (int j = 0; j < 8; j++)
        o[j] = (v[j] - mu) * inv * gamma[lane * 8 + j] + beta[lane * 8 + j];
    float* dp = out + (size_t)warp * 256 + lane * 8;
    *(float4*)(dp)     = *(float4*)&o[0];
    *(float4*)(dp + 4) = *(float4*)&o[4];
}

// ---------------- launch ----------------
extern "C" void kernel_launch(void* const* d_in, const int* in_sizes, int n_in,
                              void* d_out, int out_size)
{
    const float* source = (const float*)d_in[0];
    const float* target = (const float*)d_in[1];
    const void*  eidx   = d_in[2];
    const int base = (n_in > 3 && in_sizes[3] == 1) ? 4 : 3;
    const float* W0 = (const float*)d_in[base + 0];
    const float* b0 = (const float*)d_in[base + 1];
    const float* W1 = (const float*)d_in[base + 2];
    const float* b1 = (const float*)d_in[base + 3];
    const float* W2 = (const float*)d_in[base + 4];
    const float* b2 = (const float*)d_in[base + 5];
    const float* W3 = (const float*)d_in[base + 6];
    const float* b3 = (const float*)d_in[base + 7];
    const float* gm = (const float*)d_in[base + 8];
    const float* bt = (const float*)d_in[base + 9];

    const int M = in_sizes[0] / HDIM;
    const int E = in_sizes[2] / 2;

    float *buf1, *accum, *counts;
    cudaGetSymbolAddress((void**)&buf1,   g_buf1);
    cudaGetSymbolAddress((void**)&accum,  g_accum);
    cudaGetSymbolAddress((void**)&counts, g_counts);
    __nv_bfloat16 *a1h, *a1l, *a4h, *a4l;
    cudaGetSymbolAddress((void**)&a1h, g_a1h); cudaGetSymbolAddress((void**)&a1l, g_a1l);
    cudaGetSymbolAddress((void**)&a4h, g_a4h); cudaGetSymbolAddress((void**)&a4l, g_a4l);
    __nv_bfloat16 *w0h, *w0l, *w1h, *w1l, *w2h, *w2l, *w3h, *w3l;
    cudaGetSymbolAddress((void**)&w0h, g_w0h); cudaGetSymbolAddress((void**)&w0l, g_w0l);
    cudaGetSymbolAddress((void**)&w1h, g_w1h); cudaGetSymbolAddress((void**)&w1l, g_w1l);
    cudaGetSymbolAddress((void**)&w2h, g_w2h); cudaGetSymbolAddress((void**)&w2l, g_w2l);
    cudaGetSymbolAddress((void**)&w3h, g_w3h); cudaGetSymbolAddress((void**)&w3l, g_w3l);

    cudaFuncSetAttribute(gemm_f32in<8, 0, 1>,   cudaFuncAttributeMaxDynamicSharedMemorySize, F_SM_TOTAL);
    cudaFuncSetAttribute(gemm_f32in<16, 1, 1>,  cudaFuncAttributeMaxDynamicSharedMemorySize, F_SM_TOTAL);
    cudaFuncSetAttribute(gemm_bf16in<8, 0, 0>,  cudaFuncAttributeMaxDynamicSharedMemorySize, B_SM_TOTAL);
    cudaFuncSetAttribute(gemm_bf16in<8, 0, 1>,  cudaFuncAttributeMaxDynamicSharedMemorySize, B_SM_TOTAL);

    // Launch order keeps ncu "-s 5 -c 1" on gemm2:
    //  0 memset, 1 memset, 2 wprep, 3 detect, 4 gemm1, 5 gemm2 <- captured
    cudaMemsetAsync(accum, 0, sizeof(float) * (size_t)M * HDIM);
    cudaMemsetAsync(counts, 0, sizeof(float) * (size_t)M);
    wprep_all_kernel<<<(327680 + 255) / 256, 256>>>(W0, W1, W2, W3);
    detect_idx_kernel<<<1, 1>>>(eidx, M);

    const dim3 gG(2, (M + 63) / 64);
    // gemm1: source fp32 -> a1h/a1l (split bf16)
    gemm_f32in<8, 0, 1><<<gG, 256, F_SM_TOTAL>>>(source, nullptr, nullptr, w0h, w0l, 256,
                                                 b0, nullptr, a1h, a1l, M);
    // gemm2: a1 (bf16) -> buf1 fp32 (msg for scatter)
    gemm_bf16in<8, 0, 0><<<gG, 256, B_SM_TOTAL>>>(a1h, a1l, w1h, w1l, 256, b1, nullptr,
                                                  buf1, nullptr, nullptr, M);

    scatter_kernel<<<2960, 256>>>(eidx, buf1, accum, counts, E, M);

    // gemm3: [target | accum/cnt] fp32 (in-loop normalize+split) -> a4h/a4l
    gemm_f32in<16, 1, 1><<<gG, 256, F_SM_TOTAL>>>(target, accum, counts, w2h, w2l, 512,
                                                  b2, nullptr, a4h, a4l, M);
    // gemm4: a4 (bf16) + resid -> buf1 fp32 (pre-LN)
    gemm_bf16in<8, 0, 1><<<gG, 256, B_SM_TOTAL>>>(a4h, a4l, w3h, w3l, 256, b3, target,
                                                  buf1, nullptr, nullptr, M);

    ln_kernel<<<(M * 32 + 255) / 256, 256>>>(buf1, gm, bt, (float*)d_out, M);
}

// round 16
// speedup vs baseline: 1.1897x; 1.1788x over previous
#include <cuda_runtime.h>
#include <cuda_fp16.h>
#include <cstdint>

#define HDIM 256
#define NMAX 50048

// ---------------- static scratch ----------------
__device__ float g_buf1[NMAX * HDIM];    // gemm2 out (msg) / gemm4 out (pre-LN)
__device__ float g_accum[NMAX * HDIM];   // scatter-sum
__device__ float g_counts[NMAX];
__device__ int   g_idx64;

// pre-split fp16 activations (hi/lo) produced by GEMM epilogues
__device__ __half g_a1h[NMAX * 256], g_a1l[NMAX * 256];   // gemm1 out
__device__ __half g_a4h[NMAX * 256], g_a4l[NMAX * 256];   // gemm3 out

// fp16 weights, transposed to [N, K] (K contiguous) - single copy
__device__ __half g_w0[256 * 256];
__device__ __half g_w1[256 * 256];
__device__ __half g_w2[256 * 512];
__device__ __half g_w3[256 * 256];

__device__ __forceinline__ float gelu_exact(float x) { return x * normcdff(x); }

__device__ __forceinline__ uint32_t smem_u32(const void* p) {
    uint32_t a;
    asm("{ .reg .u64 t; cvta.to.shared.u64 t, %1; cvt.u32.u64 %0, t; }" : "=r"(a) : "l"(p));
    return a;
}

#define LDMX4(r0, r1, r2, r3, a) \
    asm volatile("ldmatrix.sync.aligned.m8n8.x4.shared.b16 {%0,%1,%2,%3}, [%4];" \
        : "=r"(r0), "=r"(r1), "=r"(r2), "=r"(r3) : "r"(a))

#define MMAF16(c, a0, a1, a2, a3, b0, b1) \
    asm volatile("mma.sync.aligned.m16n8k16.row.col.f32.f16.f16.f32 " \
        "{%0,%1,%2,%3}, {%4,%5,%6,%7}, {%8,%9}, {%0,%1,%2,%3};" \
        : "+f"((c)[0]), "+f"((c)[1]), "+f"((c)[2]), "+f"((c)[3]) \
        : "r"(a0), "r"(a1), "r"(a2), "r"(a3), "r"(b0), "r"(b1))

#define CPASYNC16(sm, gp) \
    asm volatile("cp.async.cg.shared.global [%0], [%1], 16;" :: "r"(sm), "l"(gp))
#define CPASYNC_COMMIT() asm volatile("cp.async.commit_group;" ::: "memory")
#define CPASYNC_WAIT1()  asm volatile("cp.async.wait_group 1;" ::: "memory")
#define CPASYNC_WAIT2()  asm volatile("cp.async.wait_group 2;" ::: "memory")

__device__ __forceinline__ uint32_t pack_h2(__half a, __half b) {
    __half2 t = __halves2half2(a, b);
    return *(uint32_t*)&t;
}
// fp16 hi/lo split of two floats
__device__ __forceinline__ void split2h(float v0, float v1, uint32_t& hp, uint32_t& lp) {
    __half h0 = __float2half_rn(v0);
    __half h1 = __float2half_rn(v1);
    __half l0 = __float2half_rn(v0 - __half2float(h0));
    __half l1 = __float2half_rn(v1 - __half2float(h1));
    hp = pack_h2(h0, h1);
    lp = pack_h2(l0, l1);
}

// ---------------- small kernels ----------------
__global__ void detect_idx_kernel(const void* eidx, int nnodes) {
    const long long* p = (const long long*)eidx;
    int ok64 = 1;
    #pragma unroll 1
    for (int i = 0; i < 64; i++) {
        long long v = p[i];
        if (v < 0 || v >= (long long)nnodes) { ok64 = 0; break; }
    }
    g_idx64 = ok64;
}

// all four W[K,N] fp32 -> W^T[N,K] fp16 in one launch
__global__ void wprep_all_kernel(const float* __restrict__ W0,
                                 const float* __restrict__ W1,
                                 const float* __restrict__ W2,
                                 const float* __restrict__ W3) {
    int idx = blockIdx.x * blockDim.x + threadIdx.x;
    const float* W; __half* Wt; int K;
    if (idx < 65536)       { W = W0; Wt = g_w0; K = 256; }
    else if (idx < 131072) { W = W1; Wt = g_w1; K = 256; idx -= 65536; }
    else if (idx < 262144) { W = W2; Wt = g_w2; K = 512; idx -= 131072; }
    else if (idx < 327680) { W = W3; Wt = g_w3; K = 256; idx -= 262144; }
    else return;
    const int n = idx / K, k = idx - n * K;
    Wt[idx] = __float2half_rn(W[(size_t)k * 256 + n]);
}

// ============ GEMM variant 1: fp32 A input, in-loop fp16 hi/lo split ============
// CTA 64x128, BK=32, 8 warps (2m x 4n), warp tile 32x32, 2 CTAs/SM.
// A double-buffer (reg-staged split), B single-fp16 4-stage cp.async ring.
// 2 MMAs per tile per k16: (A_hi + A_lo) x B_fp16.
#define F_SA_BASE 0
#define F_SA_STAGE 10240     /* h at +0 (5120), l at +5120 */
#define F_HLA_OFF 5120
#define F_SB_BASE 20480
#define F_SB_STAGE 10240
#define F_SM_TOTAL 61440

template<int KCHUNKS, int SPLIT, int OUTSPLIT>
__global__ __launch_bounds__(256, 2)
void gemm_f32in(const float* __restrict__ A, const float* __restrict__ A2,
                const float* __restrict__ counts,
                const __half* __restrict__ Wt,
                int Kw, const float* __restrict__ bias,
                float* __restrict__ Cf,
                __half* __restrict__ Ch, __half* __restrict__ Cl, int M)
{
    extern __shared__ char smem[];
    const uint32_t sb = smem_u32(smem);
    const int tid = threadIdx.x;
    const int wid = tid >> 5, lane = tid & 31;
    const int rowBlock = blockIdx.y * 64;
    const int colBlock = blockIdx.x * 128;

    const int warp_m = wid & 1;
    const int warp_n = wid >> 1;

    float acc[2][4][4];
    #pragma unroll
    for (int a = 0; a < 2; a++)
        #pragma unroll
        for (int b = 0; b < 4; b++)
            #pragma unroll
            for (int c = 0; c < 4; c++) acc[a][b][c] = 0.0f;

    const int arow = tid >> 2;
    const int acb  = (tid & 3) * 8;

    const int a_rowin = (lane & 7) | (((lane >> 3) & 1) << 3);
    const int a_koff  = ((lane >> 4) & 1) * 8;
    const uint32_t a_byte = (uint32_t)((warp_m * 32 + a_rowin) * 80 + a_koff * 2);
    const int b_rowin = ((lane >> 4) & 1) * 8 + (lane & 7);
    const int b_koff  = ((lane >> 3) & 1) * 8;
    const uint32_t b_byte = (uint32_t)((warp_n * 32 + b_rowin) * 80 + b_koff * 2);

    float ar[8];
    auto loadA = [&](int ch) {
        const int gr = rowBlock + arow;
        #pragma unroll
        for (int j = 0; j < 8; j++) ar[j] = 0.0f;
        if (gr < M) {
            const int gk = ch * 32 + acb;
            const float* src;
            float sc = 1.0f;
            if (SPLIT && gk >= 256) {
                src = A2 + (size_t)gr * 256 + (gk - 256);
                sc = 1.0f / fmaxf(counts[gr], 1.0f);
            } else {
                src = A + (size_t)gr * 256 + gk;
            }
            float4 v0 = *(const float4*)src;
            float4 v1 = *(const float4*)(src + 4);
            ar[0] = v0.x * sc; ar[1] = v0.y * sc; ar[2] = v0.z * sc; ar[3] = v0.w * sc;
            ar[4] = v1.x * sc; ar[5] = v1.y * sc; ar[6] = v1.z * sc; ar[7] = v1.w * sc;
        }
    };
    auto storeA = [&](int stA) {
        uint32_t hp[4], lp[4];
        #pragma unroll
        for (int j = 0; j < 4; j++) split2h(ar[2 * j], ar[2 * j + 1], hp[j], lp[j]);
        const uint32_t off = (uint32_t)(F_SA_BASE + stA * F_SA_STAGE + arow * 80 + acb * 2);
        *(uint4*)(smem + off)             = *(uint4*)&hp[0];
        *(uint4*)(smem + off + F_HLA_OFF) = *(uint4*)&lp[0];
    };
    auto issueB = [&](int ch) {
        if (ch < KCHUNKS) {
            const int st = ch & 3;
            const uint32_t bh = sb + F_SB_BASE + st * F_SB_STAGE;
            #pragma unroll
            for (int q = 0; q < 2; q++) {
                const int s = tid * 2 + q;
                const int n = s >> 2, p = s & 3;
                const size_t gofs = (size_t)(colBlock + n) * Kw + ch * 32 + p * 8;
                CPASYNC16(bh + (uint32_t)(n * 80 + p * 16), Wt + gofs);
            }
        }
        CPASYNC_COMMIT();
    };

    issueB(0);
    issueB(1);
    loadA(0);
    storeA(0);

    #pragma unroll 1
    for (int ch = 0; ch < KCHUNKS; ch++) {
        issueB(ch + 2);
        const bool more = (ch + 1 < KCHUNKS);
        if (more) loadA(ch + 1);
        CPASYNC_WAIT2();
        __syncthreads();

        const uint32_t aBase = sb + F_SA_BASE + (ch & 1) * F_SA_STAGE + a_byte;
        const uint32_t bBase = sb + F_SB_BASE + (ch & 3) * F_SB_STAGE + b_byte;
        #pragma unroll
        for (int s = 0; s < 2; s++) {
            uint32_t ah[2][4], al[2][4], bf[2][4];
            #pragma unroll
            for (int mt = 0; mt < 2; mt++) {
                LDMX4(ah[mt][0], ah[mt][1], ah[mt][2], ah[mt][3], aBase + mt * 16 * 80 + s * 32);
                LDMX4(al[mt][0], al[mt][1], al[mt][2], al[mt][3], aBase + F_HLA_OFF + mt * 16 * 80 + s * 32);
            }
            #pragma unroll
            for (int np = 0; np < 2; np++)
                LDMX4(bf[np][0], bf[np][1], bf[np][2], bf[np][3], bBase + np * 16 * 80 + s * 32);
            // pass 1: A_hi x B over all 8 tiles
            #pragma unroll
            for (int mt = 0; mt < 2; mt++)
                #pragma unroll
                for (int nt = 0; nt < 4; nt++) {
                    const int np = nt >> 1, ix = (nt & 1) * 2;
                    MMAF16(acc[mt][nt], ah[mt][0], ah[mt][1], ah[mt][2], ah[mt][3],
                           bf[np][ix], bf[np][ix + 1]);
                }
            // pass 2: A_lo x B
            #pragma unroll
            for (int mt = 0; mt < 2; mt++)
                #pragma unroll
                for (int nt = 0; nt < 4; nt++) {
                    const int np = nt >> 1, ix = (nt & 1) * 2;
                    MMAF16(acc[mt][nt], al[mt][0], al[mt][1], al[mt][2], al[mt][3],
                           bf[np][ix], bf[np][ix + 1]);
                }
        }
        if (more) storeA((ch + 1) & 1);
    }

    const int qr = lane >> 2;
    const int qc = (lane & 3) * 2;
    float bv[4][2];
    #pragma unroll
    for (int nt = 0; nt < 4; nt++) {
        const int col = colBlock + warp_n * 32 + nt * 8 + qc;
        bv[nt][0] = bias[col];
        bv[nt][1] = bias[col + 1];
    }
    #pragma unroll
    for (int mt = 0; mt < 2; mt++)
        #pragma unroll
        for (int half = 0; half < 2; half++) {
            const int row = rowBlock + warp_m * 32 + mt * 16 + qr + half * 8;
            if (row >= M) continue;
            #pragma unroll
            for (int nt = 0; nt < 4; nt++) {
                const int col = colBlock + warp_n * 32 + nt * 8 + qc;
                float v0 = gelu_exact(acc[mt][nt][half * 2 + 0] + bv[nt][0]);
                float v1 = gelu_exact(acc[mt][nt][half * 2 + 1] + bv[nt][1]);
                if (OUTSPLIT) {
                    uint32_t hp, lp;
                    split2h(v0, v1, hp, lp);
                    *(uint32_t*)(Ch + (size_t)row * 256 + col) = hp;
                    *(uint32_t*)(Cl + (size_t)row * 256 + col) = lp;
                } else {
                    *(float2*)(Cf + (size_t)row * 256 + col) = make_float2(v0, v1);
                }
            }
        }
}

// ============ GEMM variant 2: pre-split fp16 A input ============
#define B_STG_STRIDE 20480   /* Ah[0,5120) Al[5120,10240) B[10240,20480) */
#define B_SM_TOTAL (3 * B_STG_STRIDE)

template<int KCHUNKS, int OUTSPLIT, int RESID>
__global__ __launch_bounds__(256, 2)
void gemm_f16in(const __half* __restrict__ Ah, const __half* __restrict__ Al,
                const __half* __restrict__ Wt,
                int Kw, const float* __restrict__ bias, const float* __restrict__ resid,
                float* __restrict__ Cf,
                __half* __restrict__ Ch, __half* __restrict__ Cl, int M)
{
    extern __shared__ char smem[];
    const uint32_t sb = smem_u32(smem);
    const int tid = threadIdx.x;
    const int wid = tid >> 5, lane = tid & 31;
    const int rowBlock = blockIdx.y * 64;
    const int colBlock = blockIdx.x * 128;

    const int warp_m = wid & 1;
    const int warp_n = wid >> 1;

    float acc[2][4][4];
    #pragma unroll
    for (int a = 0; a < 2; a++)
        #pragma unroll
        for (int b = 0; b < 4; b++)
            #pragma unroll
            for (int c = 0; c < 4; c++) acc[a][b][c] = 0.0f;

    const int a_rowin = (lane & 7) | (((lane >> 3) & 1) << 3);
    const int a_koff  = ((lane >> 4) & 1) * 8;
    const uint32_t a_byte = (uint32_t)((warp_m * 32 + a_rowin) * 80 + a_koff * 2);
    const int b_rowin = ((lane >> 4) & 1) * 8 + (lane & 7);
    const int b_koff  = ((lane >> 3) & 1) * 8;
    const uint32_t b_byte = (uint32_t)((warp_n * 32 + b_rowin) * 80 + b_koff * 2);

    const int a_row = tid >> 2, a_p = tid & 3;
    auto issueAB = [&](int ch) {
        if (ch < KCHUNKS) {
            const uint32_t base = sb + (uint32_t)(ch % 3) * B_STG_STRIDE;
            {
                const size_t g = (size_t)(rowBlock + a_row) * Kw + ch * 32 + a_p * 8;
                const uint32_t so = (uint32_t)(a_row * 80 + a_p * 16);
                CPASYNC16(base + so, Ah + g);
                CPASYNC16(base + 5120 + so, Al + g);
            }
            #pragma unroll
            for (int q = 0; q < 2; q++) {
                const int s2 = tid * 2 + q;
                const int n = s2 >> 2, p = s2 & 3;
                const size_t g = (size_t)(colBlock + n) * Kw + ch * 32 + p * 8;
                CPASYNC16(base + 10240 + (uint32_t)(n * 80 + p * 16), Wt + g);
            }
        }
        CPASYNC_COMMIT();
    };

    issueAB(0);

    #pragma unroll 1
    for (int ch = 0; ch < KCHUNKS; ch++) {
        issueAB(ch + 1);
        CPASYNC_WAIT1();
        __syncthreads();

        const uint32_t stg = sb + (uint32_t)(ch % 3) * B_STG_STRIDE;
        const uint32_t aBase = stg + a_byte;
        const uint32_t bBase = stg + 10240 + b_byte;
        #pragma unroll
        for (int s = 0; s < 2; s++) {
            uint32_t ah[2][4], al[2][4], bf[2][4];
            #pragma unroll
            for (int mt = 0; mt < 2; mt++) {
                LDMX4(ah[mt][0], ah[mt][1], ah[mt][2], ah[mt][3], aBase + mt * 16 * 80 + s * 32);
                LDMX4(al[mt][0], al[mt][1], al[mt][2], al[mt][3], aBase + 5120 + mt * 16 * 80 + s * 32);
            }
            #pragma unroll
            for (int np = 0; np < 2; np++)
                LDMX4(bf[np][0], bf[np][1], bf[np][2], bf[np][3], bBase + np * 16 * 80 + s * 32);
            #pragma unroll
            for (int mt = 0; mt < 2; mt++)
                #pragma unroll
                for (int nt = 0; nt < 4; nt++) {
                    const int np = nt >> 1, ix = (nt & 1) * 2;
                    MMAF16(acc[mt][nt], ah[mt][0], ah[mt][1], ah[mt][2], ah[mt][3],
                           bf[np][ix], bf[np][ix + 1]);
                }
            #pragma unroll
            for (int mt = 0; mt < 2; mt++)
                #pragma unroll
                for (int nt = 0; nt < 4; nt++) {
                    const int np = nt >> 1, ix = (nt & 1) * 2;
                    MMAF16(acc[mt][nt], al[mt][0], al[mt][1], al[mt][2], al[mt][3],
                           bf[np][ix], bf[np][ix + 1]);
                }
        }
    }

    const int qr = lane >> 2;
    const int qc = (lane & 3) * 2;
    float bv[4][2];
    #pragma unroll
    for (int nt = 0; nt < 4; nt++) {
        const int col = colBlock + warp_n * 32 + nt * 8 + qc;
        bv[nt][0] = bias[col];
        bv[nt][1] = bias[col + 1];
    }
    #pragma unroll
    for (int mt = 0; mt < 2; mt++)
        #pragma unroll
        for (int half = 0; half < 2; half++) {
            const int row = rowBlock + warp_m * 32 + mt * 16 + qr + half * 8;
            if (row >= M) continue;
            #pragma unroll
            for (int nt = 0; nt < 4; nt++) {
                const int col = colBlock + warp_n * 32 + nt * 8 + qc;
                float v0 = gelu_exact(acc[mt][nt][half * 2 + 0] + bv[nt][0]);
                float v1 = gelu_exact(acc[mt][nt][half * 2 + 1] + bv[nt][1]);
                if (RESID) {
                    const float2 rv = *(const float2*)(resid + (size_t)row * 256 + col);
                    v0 += rv.x; v1 += rv.y;
                }
                if (OUTSPLIT) {
                    uint32_t hp, lp;
                    split2h(v0, v1, hp, lp);
                    *(uint32_t*)(Ch + (size_t)row * 256 + col) = hp;
                    *(uint32_t*)(Cl + (size_t)row * 256 + col) = lp;
                } else {
                    *(float2*)(Cf + (size_t)row * 256 + col) = make_float2(v0, v1);
                }
            }
        }
}

// ---------------- edge scatter-sum (2 edges per warp iteration) ----------------
__global__ void scatter_kernel(const void* __restrict__ eidx,
                               const float* __restrict__ msg,
                               float* __restrict__ accum,
                               float* __restrict__ counts,
                               int E, int Nn)
{
    const int lane = threadIdx.x & 31;
    const int warp = (blockIdx.x * blockDim.x + threadIdx.x) >> 5;
    const int nwarps = (gridDim.x * blockDim.x) >> 5;
    const int flag = g_idx64;
    const long long* p64 = (const long long*)eidx;
    const int*       p32 = (const int*)eidx;

    #pragma unroll 1
    for (int e = warp * 2; e < E; e += nwarps * 2) {
        const int e1ok = (e + 1 < E);
        int src0, dst0, src1 = 0, dst1 = 0;
        if (flag) {
            src0 = (int)p64[e]; dst0 = (int)p64[E + e];
            if (e1ok) { src1 = (int)p64[e + 1]; dst1 = (int)p64[E + e + 1]; }
        } else {
            src0 = p32[e]; dst0 = p32[E + e];
            if (e1ok) { src1 = p32[e + 1]; dst1 = p32[E + e + 1]; }
        }
        src0 = min(max(src0, 0), Nn - 1); dst0 = min(max(dst0, 0), Nn - 1);
        src1 = min(max(src1, 0), Nn - 1); dst1 = min(max(dst1, 0), Nn - 1);

        const float4* s0 = (const float4*)(msg + (size_t)src0 * 256);
        const float4* s1 = (const float4*)(msg + (size_t)src1 * 256);
        const float4 a0 = s0[lane * 2 + 0];
        const float4 a1 = s0[lane * 2 + 1];
        float4 b0 = make_float4(0.f, 0.f, 0.f, 0.f);
        float4 b1 = make_float4(0.f, 0.f, 0.f, 0.f);
        if (e1ok) { b0 = s1[lane * 2 + 0]; b1 = s1[lane * 2 + 1]; }

        float* d0 = accum + (size_t)dst0 * 256 + lane * 8;
        asm volatile("red.global.add.v4.f32 [%0], {%1,%2,%3,%4};"
                     :: "l"(d0), "f"(a0.x), "f"(a0.y), "f"(a0.z), "f"(a0.w) : "memory");
        asm volatile("red.global.add.v4.f32 [%0], {%1,%2,%3,%4};"
                     :: "l"(d0 + 4), "f"(a1.x), "f"(a1.y), "f"(a1.z), "f"(a1.w) : "memory");
        if (e1ok) {
            float* d1 = accum + (size_t)dst1 * 256 + lane * 8;
            asm volatile("red.global.add.v4.f32 [%0], {%1,%2,%3,%4};"
                         :: "l"(d1), "f"(b0.x), "f"(b0.y), "f"(b0.z), "f"(b0.w) : "memory");
            asm volatile("red.global.add.v4.f32 [%0], {%1,%2,%3,%4};"
                         :: "l"(d1 + 4), "f"(b1.x), "f"(b1.y), "f"(b1.z), "f"(b1.w) : "memory");
        }
        if (lane == 0) {
            asm volatile("red.global.add.f32 [%0], %1;"
                         :: "l"(counts + dst0), "f"(1.0f) : "memory");
            if (e1ok)
                asm volatile("red.global.add.f32 [%0], %1;"
                             :: "l"(counts + dst1), "f"(1.0f) : "memory");
        }
    }
}

// ---------------- LayerNorm (warp per row) ----------------
__global__ __launch_bounds__(256)
void ln_kernel(const float* __restrict__ X, const float* __restrict__ gamma,
               const float* __restrict__ beta, float* __restrict__ out, int M)
{
    const int warp = (blockIdx.x * blockDim.x + threadIdx.x) >> 5;
    const int lane = threadIdx.x & 31;
    if (warp >= M) return;
    const float* xp = X + (size_t)warp * 256 + lane * 8;
    float v[8];
    *(float4*)&v[0] = *(const float4*)(xp);
    *(float4*)&v[4] = *(const float4*)(xp + 4);
    float s = 0.f, sq = 0.f;
    #pragma unroll
    for (int j = 0; j < 8; j++) { s += v[j]; sq += v[j] * v[j]; }
    #pragma unroll
    for (int off = 16; off > 0; off >>= 1) {
        s  += __shfl_xor_sync(0xFFFFFFFFu, s,  off);
        sq += __shfl_xor_sync(0xFFFFFFFFu, sq, off);
    }
    const float mu  = s * (1.0f / 256.0f);
    const float var = sq * (1.0f / 256.0f) - mu * mu;
    const float inv = rsqrtf(var + 1e-5f);
    float o[8];
    #pragma unroll
    for (int j = 0; j < 8; j++)
        o[j] = (v[j] - mu) * inv * gamma[lane * 8 + j] + beta[lane * 8 + j];
    float* dp = out + (size_t)warp * 256 + lane * 8;
    *(float4*)(dp)     = *(float4*)&o[0];
    *(float4*)(dp + 4) = *(float4*)&o[4];
}

// ---------------- launch ----------------
extern "C" void kernel_launch(void* const* d_in, const int* in_sizes, int n_in,
                              void* d_out, int out_size)
{
    const float* source = (const float*)d_in[0];
    const float* target = (const float*)d_in[1];
    const void*  eidx   = d_in[2];
    const int base = (n_in > 3 && in_sizes[3] == 1) ? 4 : 3;
    const float* W0 = (const float*)d_in[base + 0];
    const float* b0 = (const float*)d_in[base + 1];
    const float* W1 = (const float*)d_in[base + 2];
    const float* b1 = (const float*)d_in[base + 3];
    const float* W2 = (const float*)d_in[base + 4];
    const float* b2 = (const float*)d_in[base + 5];
    const float* W3 = (const float*)d_in[base + 6];
    const float* b3 = (const float*)d_in[base + 7];
    const float* gm = (const float*)d_in[base + 8];
    const float* bt = (const float*)d_in[base + 9];

    const int M = in_sizes[0] / HDIM;
    const int E = in_sizes[2] / 2;

    float *buf1, *accum, *counts;
    cudaGetSymbolAddress((void**)&buf1,   g_buf1);
    cudaGetSymbolAddress((void**)&accum,  g_accum);
    cudaGetSymbolAddress((void**)&counts, g_counts);
    __half *a1h, *a1l, *a4h, *a4l, *w0, *w1, *w2, *w3;
    cudaGetSymbolAddress((void**)&a1h, g_a1h); cudaGetSymbolAddress((void**)&a1l, g_a1l);
    cudaGetSymbolAddress((void**)&a4h, g_a4h); cudaGetSymbolAddress((void**)&a4l, g_a4l);
    cudaGetSymbolAddress((void**)&w0, g_w0); cudaGetSymbolAddress((void**)&w1, g_w1);
    cudaGetSymbolAddress((void**)&w2, g_w2); cudaGetSymbolAddress((void**)&w3, g_w3);

    cudaFuncSetAttribute(gemm_f32in<8, 0, 1>,  cudaFuncAttributeMaxDynamicSharedMemorySize, F_SM_TOTAL);
    cudaFuncSetAttribute(gemm_f32in<16, 1, 1>, cudaFuncAttributeMaxDynamicSharedMemorySize, F_SM_TOTAL);
    cudaFuncSetAttribute(gemm_f16in<8, 0, 0>,  cudaFuncAttributeMaxDynamicSharedMemorySize, B_SM_TOTAL);
    cudaFuncSetAttribute(gemm_f16in<8, 0, 1>,  cudaFuncAttributeMaxDynamicSharedMemorySize, B_SM_TOTAL);

    // Launch order keeps ncu "-s 5 -c 1" on gemm2:
    //  0 memset, 1 memset, 2 wprep, 3 detect, 4 gemm1, 5 gemm2 <- captured
    cudaMemsetAsync(accum, 0, sizeof(float) * (size_t)M * HDIM);
    cudaMemsetAsync(counts, 0, sizeof(float) * (size_t)M);
    wprep_all_kernel<<<(327680 + 255) / 256, 256>>>(W0, W1, W2, W3);
    detect_idx_kernel<<<1, 1>>>(eidx, M);

    const dim3 gG(2, (M + 63) / 64);
    // gemm1: source fp32 -> a1h/a1l (split fp16)
    gemm_f32in<8, 0, 1><<<gG, 256, F_SM_TOTAL>>>(source, nullptr, nullptr, w0, 256,
                                                 b0, nullptr, a1h, a1l, M);
    // gemm2: a1 (fp16) -> buf1 fp32 (msg for scatter)
    gemm_f16in<8, 0, 0><<<gG, 256, B_SM_TOTAL>>>(a1h, a1l, w1, 256, b1, nullptr,
                                                 buf1, nullptr, nullptr, M);

    scatter_kernel<<<2960, 256>>>(eidx, buf1, accum, counts, E, M);

    // gemm3: [target | accum/cnt] fp32 (in-loop normalize+split) -> a4h/a4l
    gemm_f32in<16, 1, 1><<<gG, 256, F_SM_TOTAL>>>(target, accum, counts, w2, 512,
                                                  b2, nullptr, a4h, a4l, M);
    // gemm4: a4 (fp16) + resid -> buf1 fp32 (pre-LN)
    gemm_f16in<8, 0, 1><<<gG, 256, B_SM_TOTAL>>>(a4h, a4l, w3, 256, b3, target,
                                                 buf1, nullptr, nullptr, M);

    ln_kernel<<<(M * 32 + 255) / 256, 256>>>(buf1, gm, bt, (float*)d_out, M);
}

// round 17
// speedup vs baseline: 1.3076x; 1.0991x over previous
#include <cuda_runtime.h>
#include <cuda_fp16.h>
#include <cstdint>

#define HDIM 256
#define NMAX 50048

// ---------------- static scratch ----------------
__device__ float g_buf1[NMAX * HDIM];    // gemm2 out (msg) / gemm4 out (pre-LN)
__device__ float g_accum[NMAX * HDIM];   // scatter-sum
__device__ float g_counts[NMAX];
__device__ int   g_idx64;

// fp16 activations produced by GEMM epilogues
__device__ __half g_a1[NMAX * 256];   // gemm1 out
__device__ __half g_a4[NMAX * 256];   // gemm3 out

// fp16 weights, transposed to [N, K] (K contiguous)
__device__ __half g_w0[256 * 256];
__device__ __half g_w1[256 * 256];
__device__ __half g_w2[256 * 512];
__device__ __half g_w3[256 * 256];

__device__ __forceinline__ float gelu_exact(float x) { return x * normcdff(x); }

__device__ __forceinline__ uint32_t smem_u32(const void* p) {
    uint32_t a;
    asm("{ .reg .u64 t; cvta.to.shared.u64 t, %1; cvt.u32.u64 %0, t; }" : "=r"(a) : "l"(p));
    return a;
}

#define LDMX4(r0, r1, r2, r3, a) \
    asm volatile("ldmatrix.sync.aligned.m8n8.x4.shared.b16 {%0,%1,%2,%3}, [%4];" \
        : "=r"(r0), "=r"(r1), "=r"(r2), "=r"(r3) : "r"(a))

#define MMAF16(c, a0, a1, a2, a3, b0, b1) \
    asm volatile("mma.sync.aligned.m16n8k16.row.col.f32.f16.f16.f32 " \
        "{%0,%1,%2,%3}, {%4,%5,%6,%7}, {%8,%9}, {%0,%1,%2,%3};" \
        : "+f"((c)[0]), "+f"((c)[1]), "+f"((c)[2]), "+f"((c)[3]) \
        : "r"(a0), "r"(a1), "r"(a2), "r"(a3), "r"(b0), "r"(b1))

#define CPASYNC16(sm, gp) \
    asm volatile("cp.async.cg.shared.global [%0], [%1], 16;" :: "r"(sm), "l"(gp))
#define CPASYNC_COMMIT() asm volatile("cp.async.commit_group;" ::: "memory")
#define CPASYNC_WAIT1()  asm volatile("cp.async.wait_group 1;" ::: "memory")
#define CPASYNC_WAIT2()  asm volatile("cp.async.wait_group 2;" ::: "memory")

__device__ __forceinline__ uint32_t pack_h2(__half a, __half b) {
    __half2 t = __halves2half2(a, b);
    return *(uint32_t*)&t;
}

// ---------------- small kernels ----------------
__global__ void detect_idx_kernel(const void* eidx, int nnodes) {
    const long long* p = (const long long*)eidx;
    int ok64 = 1;
    #pragma unroll 1
    for (int i = 0; i < 64; i++) {
        long long v = p[i];
        if (v < 0 || v >= (long long)nnodes) { ok64 = 0; break; }
    }
    g_idx64 = ok64;
}

// all four W[K,N] fp32 -> W^T[N,K] fp16 in one launch
__global__ void wprep_all_kernel(const float* __restrict__ W0,
                                 const float* __restrict__ W1,
                                 const float* __restrict__ W2,
                                 const float* __restrict__ W3) {
    int idx = blockIdx.x * blockDim.x + threadIdx.x;
    const float* W; __half* Wt; int K;
    if (idx < 65536)       { W = W0; Wt = g_w0; K = 256; }
    else if (idx < 131072) { W = W1; Wt = g_w1; K = 256; idx -= 65536; }
    else if (idx < 262144) { W = W2; Wt = g_w2; K = 512; idx -= 131072; }
    else if (idx < 327680) { W = W3; Wt = g_w3; K = 256; idx -= 262144; }
    else return;
    const int n = idx / K, k = idx - n * K;
    Wt[idx] = __float2half_rn(W[(size_t)k * 256 + n]);
}

// ============ GEMM variant 1: fp32 A input, in-loop fp16 convert ============
// CTA 64x128, BK=32, 8 warps (2m x 4n), warp tile 32x32, 2 CTAs/SM.
// A double-buffer (reg-staged convert), B 4-stage cp.async ring. 1 MMA/tile/k16.
// SMEM: A stages [0,5120),[5120,10240); B stages 10240 + st*10240. Total 51200.
#define F_SA_BASE 0
#define F_SA_STAGE 5120
#define F_SB_BASE 10240
#define F_SB_STAGE 10240
#define F_SM_TOTAL 51200

template<int KCHUNKS, int SPLIT, int OUTHALF>
__global__ __launch_bounds__(256, 2)
void gemm_f32in(const float* __restrict__ A, const float* __restrict__ A2,
                const float* __restrict__ counts,
                const __half* __restrict__ Wt,
                int Kw, const float* __restrict__ bias,
                float* __restrict__ Cf, __half* __restrict__ Chf, int M)
{
    extern __shared__ char smem[];
    const uint32_t sb = smem_u32(smem);
    const int tid = threadIdx.x;
    const int wid = tid >> 5, lane = tid & 31;
    const int rowBlock = blockIdx.y * 64;
    const int colBlock = blockIdx.x * 128;

    const int warp_m = wid & 1;
    const int warp_n = wid >> 1;

    float acc[2][4][4];
    #pragma unroll
    for (int a = 0; a < 2; a++)
        #pragma unroll
        for (int b = 0; b < 4; b++)
            #pragma unroll
            for (int c = 0; c < 4; c++) acc[a][b][c] = 0.0f;

    const int arow = tid >> 2;
    const int acb  = (tid & 3) * 8;

    const int a_rowin = (lane & 7) | (((lane >> 3) & 1) << 3);
    const int a_koff  = ((lane >> 4) & 1) * 8;
    const uint32_t a_byte = (uint32_t)((warp_m * 32 + a_rowin) * 80 + a_koff * 2);
    const int b_rowin = ((lane >> 4) & 1) * 8 + (lane & 7);
    const int b_koff  = ((lane >> 3) & 1) * 8;
    const uint32_t b_byte = (uint32_t)((warp_n * 32 + b_rowin) * 80 + b_koff * 2);

    float ar[8];
    auto loadA = [&](int ch) {
        const int gr = rowBlock + arow;
        #pragma unroll
        for (int j = 0; j < 8; j++) ar[j] = 0.0f;
        if (gr < M) {
            const int gk = ch * 32 + acb;
            const float* src;
            float sc = 1.0f;
            if (SPLIT && gk >= 256) {
                src = A2 + (size_t)gr * 256 + (gk - 256);
                sc = 1.0f / fmaxf(counts[gr], 1.0f);
            } else {
                src = A + (size_t)gr * 256 + gk;
            }
            float4 v0 = *(const float4*)src;
            float4 v1 = *(const float4*)(src + 4);
            ar[0] = v0.x * sc; ar[1] = v0.y * sc; ar[2] = v0.z * sc; ar[3] = v0.w * sc;
            ar[4] = v1.x * sc; ar[5] = v1.y * sc; ar[6] = v1.z * sc; ar[7] = v1.w * sc;
        }
    };
    auto storeA = [&](int stA) {
        uint32_t hp[4];
        #pragma unroll
        for (int j = 0; j < 4; j++)
            hp[j] = pack_h2(__float2half_rn(ar[2 * j]), __float2half_rn(ar[2 * j + 1]));
        const uint32_t off = (uint32_t)(F_SA_BASE + stA * F_SA_STAGE + arow * 80 + acb * 2);
        *(uint4*)(smem + off) = *(uint4*)&hp[0];
    };
    auto issueB = [&](int ch) {
        if (ch < KCHUNKS) {
            const int st = ch & 3;
            const uint32_t bh = sb + F_SB_BASE + st * F_SB_STAGE;
            #pragma unroll
            for (int q = 0; q < 2; q++) {
                const int s = tid * 2 + q;
                const int n = s >> 2, p = s & 3;
                const size_t gofs = (size_t)(colBlock + n) * Kw + ch * 32 + p * 8;
                CPASYNC16(bh + (uint32_t)(n * 80 + p * 16), Wt + gofs);
            }
        }
        CPASYNC_COMMIT();
    };

    issueB(0);
    issueB(1);
    loadA(0);
    storeA(0);

    #pragma unroll 1
    for (int ch = 0; ch < KCHUNKS; ch++) {
        issueB(ch + 2);
        const bool more = (ch + 1 < KCHUNKS);
        if (more) loadA(ch + 1);
        CPASYNC_WAIT2();
        __syncthreads();

        const uint32_t aBase = sb + F_SA_BASE + (ch & 1) * F_SA_STAGE + a_byte;
        const uint32_t bBase = sb + F_SB_BASE + (ch & 3) * F_SB_STAGE + b_byte;
        #pragma unroll
        for (int s = 0; s < 2; s++) {
            uint32_t af[2][4], bf[2][4];
            #pragma unroll
            for (int mt = 0; mt < 2; mt++)
                LDMX4(af[mt][0], af[mt][1], af[mt][2], af[mt][3], aBase + mt * 16 * 80 + s * 32);
            #pragma unroll
            for (int np = 0; np < 2; np++)
                LDMX4(bf[np][0], bf[np][1], bf[np][2], bf[np][3], bBase + np * 16 * 80 + s * 32);
            #pragma unroll
            for (int mt = 0; mt < 2; mt++)
                #pragma unroll
                for (int nt = 0; nt < 4; nt++) {
                    const int np = nt >> 1, ix = (nt & 1) * 2;
                    MMAF16(acc[mt][nt], af[mt][0], af[mt][1], af[mt][2], af[mt][3],
                           bf[np][ix], bf[np][ix + 1]);
                }
        }
        if (more) storeA((ch + 1) & 1);
    }

    const int qr = lane >> 2;
    const int qc = (lane & 3) * 2;
    float bv[4][2];
    #pragma unroll
    for (int nt = 0; nt < 4; nt++) {
        const int col = colBlock + warp_n * 32 + nt * 8 + qc;
        bv[nt][0] = bias[col];
        bv[nt][1] = bias[col + 1];
    }
    #pragma unroll
    for (int mt = 0; mt < 2; mt++)
        #pragma unroll
        for (int half = 0; half < 2; half++) {
            const int row = rowBlock + warp_m * 32 + mt * 16 + qr + half * 8;
            if (row >= M) continue;
            #pragma unroll
            for (int nt = 0; nt < 4; nt++) {
                const int col = colBlock + warp_n * 32 + nt * 8 + qc;
                float v0 = gelu_exact(acc[mt][nt][half * 2 + 0] + bv[nt][0]);
                float v1 = gelu_exact(acc[mt][nt][half * 2 + 1] + bv[nt][1]);
                if (OUTHALF) {
                    *(uint32_t*)(Chf + (size_t)row * 256 + col) =
                        pack_h2(__float2half_rn(v0), __float2half_rn(v1));
                } else {
                    *(float2*)(Cf + (size_t)row * 256 + col) = make_float2(v0, v1);
                }
            }
        }
}

// ============ GEMM variant 2: fp16 A input ============
#define B_STG_STRIDE 15360   /* A[0,5120) B[5120,15360) */
#define B_SM_TOTAL (3 * B_STG_STRIDE)

template<int KCHUNKS, int OUTHALF, int RESID>
__global__ __launch_bounds__(256, 2)
void gemm_f16in(const __half* __restrict__ Ax,
                const __half* __restrict__ Wt,
                int Kw, const float* __restrict__ bias, const float* __restrict__ resid,
                float* __restrict__ Cf, __half* __restrict__ Chf, int M)
{
    extern __shared__ char smem[];
    const uint32_t sb = smem_u32(smem);
    const int tid = threadIdx.x;
    const int wid = tid >> 5, lane = tid & 31;
    const int rowBlock = blockIdx.y * 64;
    const int colBlock = blockIdx.x * 128;

    const int warp_m = wid & 1;
    const int warp_n = wid >> 1;

    float acc[2][4][4];
    #pragma unroll
    for (int a = 0; a < 2; a++)
        #pragma unroll
        for (int b = 0; b < 4; b++)
            #pragma unroll
            for (int c = 0; c < 4; c++) acc[a][b][c] = 0.0f;

    const int a_rowin = (lane & 7) | (((lane >> 3) & 1) << 3);
    const int a_koff  = ((lane >> 4) & 1) * 8;
    const uint32_t a_byte = (uint32_t)((warp_m * 32 + a_rowin) * 80 + a_koff * 2);
    const int b_rowin = ((lane >> 4) & 1) * 8 + (lane & 7);
    const int b_koff  = ((lane >> 3) & 1) * 8;
    const uint32_t b_byte = (uint32_t)((warp_n * 32 + b_rowin) * 80 + b_koff * 2);

    const int a_row = tid >> 2, a_p = tid & 3;
    auto issueAB = [&](int ch) {
        if (ch < KCHUNKS) {
            const uint32_t base = sb + (uint32_t)(ch % 3) * B_STG_STRIDE;
            // A: 64 rows x 32 halfs = 5120B -> 256 thr x 1x16B... 64*4=256 ok
            {
                const size_t g = (size_t)(rowBlock + a_row) * Kw + ch * 32 + a_p * 8;
                CPASYNC16(base + (uint32_t)(a_row * 80 + a_p * 16), Ax + g);
            }
            #pragma unroll
            for (int q = 0; q < 2; q++) {
                const int s2 = tid * 2 + q;
                const int n = s2 >> 2, p = s2 & 3;
                const size_t g = (size_t)(colBlock + n) * Kw + ch * 32 + p * 8;
                CPASYNC16(base + 5120 + (uint32_t)(n * 80 + p * 16), Wt + g);
            }
        }
        CPASYNC_COMMIT();
    };

    issueAB(0);

    #pragma unroll 1
    for (int ch = 0; ch < KCHUNKS; ch++) {
        issueAB(ch + 1);
        CPASYNC_WAIT1();
        __syncthreads();

        const uint32_t stg = sb + (uint32_t)(ch % 3) * B_STG_STRIDE;
        const uint32_t aBase = stg + a_byte;
        const uint32_t bBase = stg + 5120 + b_byte;
        #pragma unroll
        for (int s = 0; s < 2; s++) {
            uint32_t af[2][4], bf[2][4];
            #pragma unroll
            for (int mt = 0; mt < 2; mt++)
                LDMX4(af[mt][0], af[mt][1], af[mt][2], af[mt][3], aBase + mt * 16 * 80 + s * 32);
            #pragma unroll
            for (int np = 0; np < 2; np++)
                LDMX4(bf[np][0], bf[np][1], bf[np][2], bf[np][3], bBase + np * 16 * 80 + s * 32);
            #pragma unroll
            for (int mt = 0; mt < 2; mt++)
                #pragma unroll
                for (int nt = 0; nt < 4; nt++) {
                    const int np = nt >> 1, ix = (nt & 1) * 2;
                    MMAF16(acc[mt][nt], af[mt][0], af[mt][1], af[mt][2], af[mt][3],
                           bf[np][ix], bf[np][ix + 1]);
                }
        }
    }

    const int qr = lane >> 2;
    const int qc = (lane & 3) * 2;
    float bv[4][2];
    #pragma unroll
    for (int nt = 0; nt < 4; nt++) {
        const int col = colBlock + warp_n * 32 + nt * 8 + qc;
        bv[nt][0] = bias[col];
        bv[nt][1] = bias[col + 1];
    }
    #pragma unroll
    for (int mt = 0; mt < 2; mt++)
        #pragma unroll
        for (int half = 0; half < 2; half++) {
            const int row = rowBlock + warp_m * 32 + mt * 16 + qr + half * 8;
            if (row >= M) continue;
            #pragma unroll
            for (int nt = 0; nt < 4; nt++) {
                const int col = colBlock + warp_n * 32 + nt * 8 + qc;
                float v0 = gelu_exact(acc[mt][nt][half * 2 + 0] + bv[nt][0]);
                float v1 = gelu_exact(acc[mt][nt][half * 2 + 1] + bv[nt][1]);
                if (RESID) {
                    const float2 rv = *(const float2*)(resid + (size_t)row * 256 + col);
                    v0 += rv.x; v1 += rv.y;
                }
                if (OUTHALF) {
                    *(uint32_t*)(Chf + (size_t)row * 256 + col) =
                        pack_h2(__float2half_rn(v0), __float2half_rn(v1));
                } else {
                    *(float2*)(Cf + (size_t)row * 256 + col) = make_float2(v0, v1);
                }
            }
        }
}

// ---------------- edge scatter-sum (2 edges per warp iteration) ----------------
__global__ void scatter_kernel(const void* __restrict__ eidx,
                               const float* __restrict__ msg,
                               float* __restrict__ accum,
                               float* __restrict__ counts,
                               int E, int Nn)
{
    const int lane = threadIdx.x & 31;
    const int warp = (blockIdx.x * blockDim.x + threadIdx.x) >> 5;
    const int nwarps = (gridDim.x * blockDim.x) >> 5;
    const int flag = g_idx64;
    const long long* p64 = (const long long*)eidx;
    const int*       p32 = (const int*)eidx;

    #pragma unroll 1
    for (int e = warp * 2; e < E; e += nwarps * 2) {
        const int e1ok = (e + 1 < E);
        int src0, dst0, src1 = 0, dst1 = 0;
        if (flag) {
            src0 = (int)p64[e]; dst0 = (int)p64[E + e];
            if (e1ok) { src1 = (int)p64[e + 1]; dst1 = (int)p64[E + e + 1]; }
        } else {
            src0 = p32[e]; dst0 = p32[E + e];
            if (e1ok) { src1 = p32[e + 1]; dst1 = p32[E + e + 1]; }
        }
        src0 = min(max(src0, 0), Nn - 1); dst0 = min(max(dst0, 0), Nn - 1);
        src1 = min(max(src1, 0), Nn - 1); dst1 = min(max(dst1, 0), Nn - 1);

        const float4* s0 = (const float4*)(msg + (size_t)src0 * 256);
        const float4* s1 = (const float4*)(msg + (size_t)src1 * 256);
        const float4 a0 = s0[lane * 2 + 0];
        const float4 a1 = s0[lane * 2 + 1];
        float4 b0 = make_float4(0.f, 0.f, 0.f, 0.f);
        float4 b1 = make_float4(0.f, 0.f, 0.f, 0.f);
        if (e1ok) { b0 = s1[lane * 2 + 0]; b1 = s1[lane * 2 + 1]; }

        float* d0 = accum + (size_t)dst0 * 256 + lane * 8;
        asm volatile("red.global.add.v4.f32 [%0], {%1,%2,%3,%4};"
                     :: "l"(d0), "f"(a0.x), "f"(a0.y), "f"(a0.z), "f"(a0.w) : "memory");
        asm volatile("red.global.add.v4.f32 [%0], {%1,%2,%3,%4};"
                     :: "l"(d0 + 4), "f"(a1.x), "f"(a1.y), "f"(a1.z), "f"(a1.w) : "memory");
        if (e1ok) {
            float* d1 = accum + (size_t)dst1 * 256 + lane * 8;
            asm volatile("red.global.add.v4.f32 [%0], {%1,%2,%3,%4};"
                         :: "l"(d1), "f"(b0.x), "f"(b0.y), "f"(b0.z), "f"(b0.w) : "memory");
            asm volatile("red.global.add.v4.f32 [%0], {%1,%2,%3,%4};"
                         :: "l"(d1 + 4), "f"(b1.x), "f"(b1.y), "f"(b1.z), "f"(b1.w) : "memory");
        }
        if (lane == 0) {
            asm volatile("red.global.add.f32 [%0], %1;"
                         :: "l"(counts + dst0), "f"(1.0f) : "memory");
            if (e1ok)
                asm volatile("red.global.add.f32 [%0], %1;"
                             :: "l"(counts + dst1), "f"(1.0f) : "memory");
        }
    }
}

// ---------------- LayerNorm (warp per row) ----------------
__global__ __launch_bounds__(256)
void ln_kernel(const float* __restrict__ X, const float* __restrict__ gamma,
               const float* __restrict__ beta, float* __restrict__ out, int M)
{
    const int warp = (blockIdx.x * blockDim.x + threadIdx.x) >> 5;
    const int lane = threadIdx.x & 31;
    if (warp >= M) return;
    const float* xp = X + (size_t)warp * 256 + lane * 8;
    float v[8];
    *(float4*)&v[0] = *(const float4*)(xp);
    *(float4*)&v[4] = *(const float4*)(xp + 4);
    float s = 0.f, sq = 0.f;
    #pragma unroll
    for (int j = 0; j < 8; j++) { s += v[j]; sq += v[j] * v[j]; }
    #pragma unroll
    for (int off = 16; off > 0; off >>= 1) {
        s  += __shfl_xor_sync(0xFFFFFFFFu, s,  off);
        sq += __shfl_xor_sync(0xFFFFFFFFu, sq, off);
    }
    const float mu  = s * (1.0f / 256.0f);
    const float var = sq * (1.0f / 256.0f) - mu * mu;
    const float inv = rsqrtf(var + 1e-5f);
    float o[8];
    #pragma unroll
    for (int j = 0; j < 8; j++)
        o[j] = (v[j] - mu) * inv * gamma[lane * 8 + j] + beta[lane * 8 + j];
    float* dp = out + (size_t)warp * 256 + lane * 8;
    *(float4*)(dp)     = *(float4*)&o[0];
    *(float4*)(dp + 4) = *(float4*)&o[4];
}

// ---------------- launch ----------------
extern "C" void kernel_launch(void* const* d_in, const int* in_sizes, int n_in,
                              void* d_out, int out_size)
{
    const float* source = (const float*)d_in[0];
    const float* target = (const float*)d_in[1];
    const void*  eidx   = d_in[2];
    const int base = (n_in > 3 && in_sizes[3] == 1) ? 4 : 3;
    const float* W0 = (const float*)d_in[base + 0];
    const float* b0 = (const float*)d_in[base + 1];
    const float* W1 = (const float*)d_in[base + 2];
    const float* b1 = (const float*)d_in[base + 3];
    const float* W2 = (const float*)d_in[base + 4];
    const float* b2 = (const float*)d_in[base + 5];
    const float* W3 = (const float*)d_in[base + 6];
    const float* b3 = (const float*)d_in[base + 7];
    const float* gm = (const float*)d_in[base + 8];
    const float* bt = (const float*)d_in[base + 9];

    const int M = in_sizes[0] / HDIM;
    const int E = in_sizes[2] / 2;

    float *buf1, *accum, *counts;
    cudaGetSymbolAddress((void**)&buf1,   g_buf1);
    cudaGetSymbolAddress((void**)&accum,  g_accum);
    cudaGetSymbolAddress((void**)&counts, g_counts);
    __half *a1, *a4, *w0, *w1, *w2, *w3;
    cudaGetSymbolAddress((void**)&a1, g_a1); cudaGetSymbolAddress((void**)&a4, g_a4);
    cudaGetSymbolAddress((void**)&w0, g_w0); cudaGetSymbolAddress((void**)&w1, g_w1);
    cudaGetSymbolAddress((void**)&w2, g_w2); cudaGetSymbolAddress((void**)&w3, g_w3);

    cudaFuncSetAttribute(gemm_f32in<8, 0, 1>,  cudaFuncAttributeMaxDynamicSharedMemorySize, F_SM_TOTAL);
    cudaFuncSetAttribute(gemm_f32in<16, 1, 1>, cudaFuncAttributeMaxDynamicSharedMemorySize, F_SM_TOTAL);
    cudaFuncSetAttribute(gemm_f16in<8, 0, 0>,  cudaFuncAttributeMaxDynamicSharedMemorySize, B_SM_TOTAL);
    cudaFuncSetAttribute(gemm_f16in<8, 0, 1>,  cudaFuncAttributeMaxDynamicSharedMemorySize, B_SM_TOTAL);

    // Launch order keeps ncu "-s 5 -c 1" on gemm2:
    //  0 memset, 1 memset, 2 wprep, 3 detect, 4 gemm1, 5 gemm2 <- captured
    cudaMemsetAsync(accum, 0, sizeof(float) * (size_t)M * HDIM);
    cudaMemsetAsync(counts, 0, sizeof(float) * (size_t)M);
    wprep_all_kernel<<<(327680 + 255) / 256, 256>>>(W0, W1, W2, W3);
    detect_idx_kernel<<<1, 1>>>(eidx, M);

    const dim3 gG(2, (M + 63) / 64);
    // gemm1: source fp32 -> a1 (fp16)
    gemm_f32in<8, 0, 1><<<gG, 256, F_SM_TOTAL>>>(source, nullptr, nullptr, w0, 256,
                                                 b0, nullptr, a1, M);
    // gemm2: a1 (fp16) -> buf1 fp32 (msg for scatter)
    gemm_f16in<8, 0, 0><<<gG, 256, B_SM_TOTAL>>>(a1, w1, 256, b1, nullptr,
                                                 buf1, nullptr, M);

    scatter_kernel<<<2960, 256>>>(eidx, buf1, accum, counts, E, M);

    // gemm3: [target | accum/cnt] fp32 (in-loop normalize+convert) -> a4 (fp16)
    gemm_f32in<16, 1, 1><<<gG, 256, F_SM_TOTAL>>>(target, accum, counts, w2, 512,
                                                  b2, nullptr, a4, M);
    // gemm4: a4 (fp16) + resid -> buf1 fp32 (pre-LN)
    gemm_f16in<8, 0, 1><<<gG, 256, B_SM_TOTAL>>>(a4, w3, 256, b3, target,
                                                 buf1, nullptr, M);

    ln_kernel<<<(M * 32 + 255) / 256, 256>>>(buf1, gm, bt, (float*)d_out, M);
}